// round 3
// baseline (speedup 1.0000x reference)
#include <cuda_runtime.h>
#include <math.h>

// Problem constants
#define Bn 4
#define Tn 1024
#define Cn 1024
#define Hn 16
#define Dn 64
constexpr int BT  = Bn * Tn;          // 4096 rows
constexpr int BH  = Bn * Hn;          // 64 batched heads
constexpr int NQKV = 3 * Cn;          // 3072

// ---------------- scratch (static device allocations; no cudaMalloc) ------
__device__ float g_qkv[BT * NQKV];            // 4096 x 3072   (48 MB)
__device__ float g_Lq [BH * Tn * Dn];         // 64 x 1024 x 64 (16 MB)
__device__ float g_Lk [BH * Tn * Dn];         // space part negated
__device__ float g_V  [BH * Tn * Dn];
__device__ float g_S  [67108864];             // 64 x 1024 x 1024 (256 MB) scores->P in place
__device__ float g_y  [BT * Cn];              // 16 MB
__device__ float g_spike[BT];

// ---------------- 1) spike gate: sigmoid(x . w_sur + b) > thr -------------
__global__ void spike_kernel(const float* __restrict__ x,
                             const float* __restrict__ w_sur,
                             const float* __restrict__ b_sur,
                             const float* __restrict__ thr) {
    int row = blockIdx.x;                      // 0..4095
    const float4* xr = reinterpret_cast<const float4*>(x + (long long)row * Cn);
    const float4* wr = reinterpret_cast<const float4*>(w_sur);
    float s = 0.f;
    for (int i = threadIdx.x; i < Cn / 4; i += blockDim.x) {
        float4 a = xr[i], w = wr[i];
        s += a.x * w.x + a.y * w.y + a.z * w.z + a.w * w.w;
    }
    #pragma unroll
    for (int o = 16; o; o >>= 1) s += __shfl_xor_sync(0xffffffffu, s, o);
    __shared__ float sm[4];
    if ((threadIdx.x & 31) == 0) sm[threadIdx.x >> 5] = s;
    __syncthreads();
    if (threadIdx.x == 0) {
        float z = sm[0] + sm[1] + sm[2] + sm[3] + b_sur[0];
        float imp = 1.f / (1.f + expf(-z));
        g_spike[row] = (imp > thr[0]) ? 1.f : 0.f;
    }
}

// ---------------- generic register-blocked SGEMM --------------------------
// C[z] = A[z] @ B[z] + bias ; row-major; all dims divisible by tiles.
template<int BM, int BN, int BK, int TM, int TN>
__global__ void sgemm_kernel(const float* __restrict__ A, int lda, long long sA,
                             const float* __restrict__ Bm, int ldb, long long sB,
                             float* __restrict__ Cm, int ldc,
                             int cdiv, long long sC_hi, long long sC_lo,
                             int K, const float* __restrict__ bias) {
    constexpr int THREADS = (BM / TM) * (BN / TN);
    __shared__ float As[BK][BM];
    __shared__ float Bs[BK][BN];

    int z = blockIdx.z;
    const float* Ab = A  + (long long)z * sA;
    const float* Bb = Bm + (long long)z * sB;
    float*       Cb = Cm + (long long)(z / cdiv) * sC_hi + (long long)(z % cdiv) * sC_lo;

    int m0 = blockIdx.y * BM;
    int n0 = blockIdx.x * BN;
    int tid = threadIdx.x;
    int tx = tid % (BN / TN);
    int ty = tid / (BN / TN);

    float acc[TM][TN];
    #pragma unroll
    for (int i = 0; i < TM; i++)
        #pragma unroll
        for (int j = 0; j < TN; j++) acc[i][j] = 0.f;

    for (int k0 = 0; k0 < K; k0 += BK) {
        // A tile (BM x BK) -> As transposed [k][m]
        #pragma unroll
        for (int idx = tid * 4; idx < BM * BK; idx += THREADS * 4) {
            int r = idx / BK, c = idx % BK;
            float4 v = *reinterpret_cast<const float4*>(Ab + (long long)(m0 + r) * lda + k0 + c);
            As[c + 0][r] = v.x; As[c + 1][r] = v.y; As[c + 2][r] = v.z; As[c + 3][r] = v.w;
        }
        // B tile (BK x BN) -> Bs [k][n]
        #pragma unroll
        for (int idx = tid * 4; idx < BK * BN; idx += THREADS * 4) {
            int r = idx / BN, c = idx % BN;
            *reinterpret_cast<float4*>(&Bs[r][c]) =
                *reinterpret_cast<const float4*>(Bb + (long long)(k0 + r) * ldb + n0 + c);
        }
        __syncthreads();
        #pragma unroll
        for (int k = 0; k < BK; k++) {
            float af[TM], bf[TN];
            #pragma unroll
            for (int i = 0; i < TM; i += 4)
                *reinterpret_cast<float4*>(&af[i]) = *reinterpret_cast<const float4*>(&As[k][ty * TM + i]);
            #pragma unroll
            for (int j = 0; j < TN; j += 4)
                *reinterpret_cast<float4*>(&bf[j]) = *reinterpret_cast<const float4*>(&Bs[k][tx * TN + j]);
            #pragma unroll
            for (int i = 0; i < TM; i++)
                #pragma unroll
                for (int j = 0; j < TN; j++) acc[i][j] += af[i] * bf[j];
        }
        __syncthreads();
    }
    #pragma unroll
    for (int i = 0; i < TM; i++) {
        long long mi = m0 + ty * TM + i;
        #pragma unroll
        for (int j = 0; j < TN; j++) {
            int nj = n0 + tx * TN + j;
            float v = acc[i][j];
            if (bias) v += bias[nj];
            Cb[mi * ldc + nj] = v;
        }
    }
}

// ---------------- 3) expmap0 split -> Lorentz vectors + V copy ------------
// one warp per (b,h,t)
__global__ void expmap_kernel() {
    int wid  = (blockIdx.x * blockDim.x + threadIdx.x) >> 5;
    int lane = threadIdx.x & 31;
    if (wid >= BH * Tn) return;
    int bh = wid >> 10;                 // /T
    int t  = wid & (Tn - 1);
    int b  = bh >> 4;                   // /H
    int h  = bh & (Hn - 1);
    long long base = (long long)(b * Tn + t) * NQKV + h * Dn;
    const float* q = g_qkv + base;
    const float* k = q + Cn;
    const float* v = q + 2 * Cn;
    long long o = (long long)wid * Dn;

    // --- q ---
    {
        float u0v = q[lane], u1v = q[lane + 32];
        float ss = u0v * u0v + u1v * u1v;
        #pragma unroll
        for (int off = 16; off; off >>= 1) ss += __shfl_xor_sync(0xffffffffu, ss, off);
        float u0 = __shfl_sync(0xffffffffu, u0v, 0);
        float mink = ss - 2.f * u0 * u0;             // -u0^2 + sum_{1..63}
        float nom  = sqrtf(fmaxf(mink, 1e-8f));
        float tq   = coshf(nom);
        float fac  = sinhf(nom) / nom;
        g_Lq[o + lane]      = (lane == 0) ? tq : fac * u0v;
        g_Lq[o + lane + 32] = fac * u1v;
    }
    // --- k (space part negated so score = plain dot) ---
    {
        float u0v = k[lane], u1v = k[lane + 32];
        float ss = u0v * u0v + u1v * u1v;
        #pragma unroll
        for (int off = 16; off; off >>= 1) ss += __shfl_xor_sync(0xffffffffu, ss, off);
        float u0 = __shfl_sync(0xffffffffu, u0v, 0);
        float mink = ss - 2.f * u0 * u0;
        float nom  = sqrtf(fmaxf(mink, 1e-8f));
        float tk   = coshf(nom);
        float fac  = sinhf(nom) / nom;
        g_Lk[o + lane]      = (lane == 0) ? tk : -fac * u0v;
        g_Lk[o + lane + 32] = -fac * u1v;
    }
    // --- V copy to contiguous [bh][t][d] ---
    g_V[o + lane]      = v[lane];
    g_V[o + lane + 32] = v[lane + 32];
}

// ---------------- 4) scores: batched 64-dot NT GEMM + acosh epilogue ------
// grid (jtile=16, itile=16, bh=64), 256 threads, 64x64 tile, full K=64 in smem.
__global__ void score_kernel() {
    int i0 = blockIdx.y * 64;
    int j0 = blockIdx.x * 64;
    int bh = blockIdx.z;
    if (j0 > i0 + 63) return;                 // fully above diagonal; never read

    __shared__ float AqT[64][68];             // [d][i], padded
    __shared__ float BkT[64][68];             // [d][j]
    const float* Lq = g_Lq + (long long)bh * Tn * Dn;
    const float* Lk = g_Lk + (long long)bh * Tn * Dn;
    int tid = threadIdx.x;

    #pragma unroll
    for (int v = 0; v < 4; v++) {
        int f = tid + v * 256;                // float4 index 0..1023
        int r = f >> 4;                       // row 0..63
        int c = (f & 15) * 4;                 // col 0..60
        float4 q4 = *reinterpret_cast<const float4*>(Lq + (long long)(i0 + r) * Dn + c);
        AqT[c + 0][r] = q4.x; AqT[c + 1][r] = q4.y; AqT[c + 2][r] = q4.z; AqT[c + 3][r] = q4.w;
        float4 k4 = *reinterpret_cast<const float4*>(Lk + (long long)(j0 + r) * Dn + c);
        BkT[c + 0][r] = k4.x; BkT[c + 1][r] = k4.y; BkT[c + 2][r] = k4.z; BkT[c + 3][r] = k4.w;
    }
    __syncthreads();

    int tx = tid & 15, ty = tid >> 4;
    float acc[4][4];
    #pragma unroll
    for (int i = 0; i < 4; i++)
        #pragma unroll
        for (int j = 0; j < 4; j++) acc[i][j] = 0.f;

    #pragma unroll 8
    for (int d = 0; d < 64; d++) {
        float af[4], bf[4];
        *reinterpret_cast<float4*>(af) = *reinterpret_cast<const float4*>(&AqT[d][ty * 4]);
        *reinterpret_cast<float4*>(bf) = *reinterpret_cast<const float4*>(&BkT[d][tx * 4]);
        #pragma unroll
        for (int i = 0; i < 4; i++)
            #pragma unroll
            for (int j = 0; j < 4; j++) acc[i][j] += af[i] * bf[j];
    }

    float* Sb = g_S + (long long)bh * Tn * Tn;
    #pragma unroll
    for (int ii = 0; ii < 4; ii++) {
        int i = i0 + ty * 4 + ii;
        #pragma unroll
        for (int jj = 0; jj < 4; jj++) {
            int j = j0 + tx * 4 + jj;
            float s;
            if (j > i) {
                s = -INFINITY;
            } else {
                float v = fmaxf(acc[ii][jj], 1.0f + 1e-7f);
                float dd = acoshf(v);
                s = -dd * dd * 0.125f;         // / sqrt(64)
            }
            Sb[(long long)i * Tn + j] = s;
        }
    }
}

// ---------------- 5) causal softmax (in place) * spike(query) -------------
// one block (128 thr) per row; rows with spike==0 just write zeros.
__global__ void softmax_kernel() {
    int row = blockIdx.x;                     // bh*T + i
    int i   = row & (Tn - 1);
    int bh  = row >> 10;
    int b   = bh >> 4;
    float spike = g_spike[b * Tn + i];
    float* S = g_S + (long long)row * Tn;
    int tid = threadIdx.x;

    if (spike == 0.f) {
        for (int j = tid; j < Tn; j += 128) S[j] = 0.f;
        return;
    }
    int nvalid = i + 1;
    float m = -INFINITY;
    for (int j = tid; j < nvalid; j += 128) m = fmaxf(m, S[j]);
    #pragma unroll
    for (int o = 16; o; o >>= 1) m = fmaxf(m, __shfl_xor_sync(0xffffffffu, m, o));
    __shared__ float smax[4], ssum[4];
    if ((tid & 31) == 0) smax[tid >> 5] = m;
    __syncthreads();
    m = fmaxf(fmaxf(smax[0], smax[1]), fmaxf(smax[2], smax[3]));

    float l = 0.f;
    for (int j = tid; j < nvalid; j += 128) l += expf(S[j] - m);
    #pragma unroll
    for (int o = 16; o; o >>= 1) l += __shfl_xor_sync(0xffffffffu, l, o);
    if ((tid & 31) == 0) ssum[tid >> 5] = l;
    __syncthreads();
    l = ssum[0] + ssum[1] + ssum[2] + ssum[3];
    float inv = 1.f / l;

    for (int j = tid; j < Tn; j += 128) {
        float p = (j < nvalid) ? expf(S[j] - m) * inv : 0.f;
        S[j] = p;
    }
}

// ---------------- launch ---------------------------------------------------
extern "C" void kernel_launch(void* const* d_in, const int* in_sizes, int n_in,
                              void* d_out, int out_size) {
    const float* x     = (const float*)d_in[0];
    const float* W_qkv = (const float*)d_in[1];
    const float* b_qkv = (const float*)d_in[2];
    const float* W_out = (const float*)d_in[3];
    const float* b_out = (const float*)d_in[4];
    const float* w_sur = (const float*)d_in[5];
    const float* b_sur = (const float*)d_in[6];
    const float* thr   = (const float*)d_in[7];
    float* out = (float*)d_out;

    float *p_qkv, *p_S, *p_V, *p_y;
    cudaGetSymbolAddress((void**)&p_qkv, g_qkv);
    cudaGetSymbolAddress((void**)&p_S,   g_S);
    cudaGetSymbolAddress((void**)&p_V,   g_V);
    cudaGetSymbolAddress((void**)&p_y,   g_y);

    // 1) spike gate
    spike_kernel<<<BT, 128>>>(x, w_sur, b_sur, thr);

    // 2) QKV GEMM: (4096x1024)@(1024x3072)+b
    {
        dim3 grid(NQKV / 128, BT / 128, 1);
        sgemm_kernel<128, 128, 8, 8, 8><<<grid, 256>>>(
            x, Cn, 0, W_qkv, NQKV, 0, p_qkv, NQKV, 1, 0, 0, Cn, b_qkv);
    }
    // 3) expmap + V repack
    expmap_kernel<<<(BH * Tn) / 8, 256>>>();

    // 4) scores
    {
        dim3 grid(16, 16, BH);
        score_kernel<<<grid, 256>>>();
    }
    // 5) softmax
    softmax_kernel<<<BH * Tn, 128>>>();

    // 6) P@V batched: per bh (1024x1024)@(1024x64) -> y[b][t][h*64+d]
    {
        dim3 grid(1, Tn / 128, BH);
        sgemm_kernel<128, 64, 8, 8, 4><<<grid, 256>>>(
            p_S, Tn, (long long)Tn * Tn,
            p_V, Dn, (long long)Tn * Dn,
            p_y, Cn, Hn, (long long)Tn * Cn, Dn,
            Tn, nullptr);
    }
    // 7) output GEMM: (4096x1024)@(1024x1024)+b
    {
        dim3 grid(Cn / 128, BT / 128, 1);
        sgemm_kernel<128, 128, 8, 8, 8><<<grid, 256>>>(
            p_y, Cn, 0, W_out, Cn, 0, out, Cn, 1, 0, 0, Cn, b_out);
    }
}

// round 5
// speedup vs baseline: 1.3842x; 1.3842x over previous
#include <cuda_runtime.h>
#include <math.h>
#include <stdint.h>

// Problem constants
#define Bn 4
#define Tn 1024
#define Cn 1024
#define Hn 16
#define Dn 64
constexpr int BT   = Bn * Tn;          // 4096
constexpr int BH   = Bn * Hn;          // 64
constexpr int NQKV = 3 * Cn;           // 3072

// ---------------- scratch (static device allocations) ---------------------
__device__ float g_qkv[BT * NQKV];            // 48 MB
__device__ float g_Lq [BH * Tn * Dn];         // 16 MB
__device__ float g_Lk [BH * Tn * Dn];
__device__ float g_V  [BH * Tn * Dn];
__device__ float g_S  [67108864];             // 256 MB scores -> P in place
__device__ float g_y  [BT * Cn];              // 16 MB
__device__ float g_spike[BT];

// ======================= helpers ==========================================
__device__ __forceinline__ uint32_t smem_u32(const void* p) {
    uint32_t a;
    asm("{ .reg .u64 t; cvta.to.shared.u64 t, %1; cvt.u32.u64 %0, t; }" : "=r"(a) : "l"(p));
    return a;
}
__device__ __forceinline__ uint32_t cvt_tf32(float x) {
    uint32_t r; asm("cvt.rna.tf32.f32 %0, %1;" : "=r"(r) : "f"(x)); return r;
}
__device__ __forceinline__ void mma_tf32(float* c, const uint32_t* a, const uint32_t* b) {
    asm volatile(
        "mma.sync.aligned.m16n8k8.row.col.f32.tf32.tf32.f32 "
        "{%0,%1,%2,%3}, {%4,%5,%6,%7}, {%8,%9}, {%0,%1,%2,%3};"
        : "+f"(c[0]), "+f"(c[1]), "+f"(c[2]), "+f"(c[3])
        : "r"(a[0]), "r"(a[1]), "r"(a[2]), "r"(a[3]), "r"(b[0]), "r"(b[1]));
}
__device__ __forceinline__ void cp_async16(uint32_t dst, const void* src) {
    asm volatile("cp.async.cg.shared.global [%0], [%1], 16;" :: "r"(dst), "l"(src));
}

// ======================= tf32 3x mma.sync GEMM ============================
// C[z] = A_f32[z](M x K, row-major) @ B_f32[z](K x N, row-major) + bias
// Block 128 x BN, BK=32, cp.async double-buffered. Warps 2(M) x 4(N).
template<int BN>
__global__ __launch_bounds__(256, 1)
void mma_gemm(const float* __restrict__ A, int lda, long long sAz,
              const float* __restrict__ Bg, int ldb, long long sBz,
              float* __restrict__ Cm, int ldc,
              int cdiv, long long sC_hi, long long sC_lo,
              int K, const float* __restrict__ bias) {
    constexpr int SA   = 36;            // A smem row stride (floats) -> conflict-free
    constexpr int SB   = BN + 4;        // B smem row stride (floats)
    constexpr int A_EL = 128 * SA;
    constexpr int B_EL = 32 * SB;
    constexpr int WN   = BN / 4;        // warp N extent (32 or 16)
    constexpr int NT   = WN / 8;        // n8 tiles per warp (4 or 2)
    constexpr int BSEG = BN / 4;        // 16B segments per B row

    extern __shared__ float sm[];
    float* smA = sm;
    float* smB = sm + 2 * A_EL;
    uint32_t smA_u = smem_u32(smA);
    uint32_t smB_u = smem_u32(smB);

    const int tid  = threadIdx.x;
    const int lane = tid & 31;
    const int wid  = tid >> 5;
    const int wm   = wid & 1;           // 0..1
    const int wn   = wid >> 1;          // 0..3
    const int gid  = lane >> 2;         // 0..7
    const int tig  = lane & 3;          // 0..3

    const int z  = blockIdx.z;
    const int n0 = blockIdx.x * BN;
    const float* Ab = A  + (long long)z * sAz + (long long)blockIdx.y * 128 * lda;
    const float* Bb = Bg + (long long)z * sBz;
    float*       Cb = Cm + (long long)(z / cdiv) * sC_hi + (long long)(z % cdiv) * sC_lo;

    const int NC = K >> 5;

    float acc[4][NT][4];
    #pragma unroll
    for (int mt = 0; mt < 4; mt++)
        #pragma unroll
        for (int nt = 0; nt < NT; nt++)
            #pragma unroll
            for (int i = 0; i < 4; i++) acc[mt][nt][i] = 0.f;

    auto load_chunk = [&](int c, int st) {
        #pragma unroll
        for (int j = 0; j < 4; j++) {                    // A: 128x32 f32
            int idx = tid + j * 256;
            int r = idx >> 3, s = idx & 7;
            cp_async16(smA_u + (uint32_t)((st * A_EL + r * SA + s * 4) << 2),
                       Ab + (long long)r * lda + c * 32 + s * 4);
        }
        #pragma unroll
        for (int j = 0; j < (32 * BSEG) / 256; j++) {    // B: 32xBN f32
            int idx = tid + j * 256;
            int r = idx / BSEG, s = idx % BSEG;
            cp_async16(smB_u + (uint32_t)((st * B_EL + r * SB + s * 4) << 2),
                       Bb + (long long)(c * 32 + r) * ldb + n0 + s * 4);
        }
        asm volatile("cp.async.commit_group;" ::: "memory");
    };

    load_chunk(0, 0);
    for (int c = 0; c < NC; c++) {
        const int st = c & 1;
        if (c + 1 < NC) {
            load_chunk(c + 1, st ^ 1);
            asm volatile("cp.async.wait_group 1;" ::: "memory");
        } else {
            asm volatile("cp.async.wait_group 0;" ::: "memory");
        }
        __syncthreads();

        const float* cA = smA + st * A_EL;
        const float* cB = smB + st * B_EL;
        #pragma unroll
        for (int ks = 0; ks < 4; ks++) {
            const int k0 = ks * 8;
            uint32_t ah[4][4], al[4][4];
            #pragma unroll
            for (int mt = 0; mt < 4; mt++) {
                const float* p = cA + (wm * 64 + mt * 16 + gid) * SA + k0 + tig;
                float a0 = p[0], a1 = p[8 * SA], a2 = p[4], a3 = p[8 * SA + 4];
                ah[mt][0] = cvt_tf32(a0); al[mt][0] = cvt_tf32(a0 - __uint_as_float(ah[mt][0]));
                ah[mt][1] = cvt_tf32(a1); al[mt][1] = cvt_tf32(a1 - __uint_as_float(ah[mt][1]));
                ah[mt][2] = cvt_tf32(a2); al[mt][2] = cvt_tf32(a2 - __uint_as_float(ah[mt][2]));
                ah[mt][3] = cvt_tf32(a3); al[mt][3] = cvt_tf32(a3 - __uint_as_float(ah[mt][3]));
            }
            uint32_t bh[NT][2], bl[NT][2];
            #pragma unroll
            for (int nt = 0; nt < NT; nt++) {
                const float* p = cB + (k0 + tig) * SB + wn * WN + nt * 8 + gid;
                float b0 = p[0], b1 = p[4 * SB];
                bh[nt][0] = cvt_tf32(b0); bl[nt][0] = cvt_tf32(b0 - __uint_as_float(bh[nt][0]));
                bh[nt][1] = cvt_tf32(b1); bl[nt][1] = cvt_tf32(b1 - __uint_as_float(bh[nt][1]));
            }
            #pragma unroll
            for (int mt = 0; mt < 4; mt++)
                #pragma unroll
                for (int nt = 0; nt < NT; nt++) {
                    mma_tf32(acc[mt][nt], al[mt], bh[nt]);
                    mma_tf32(acc[mt][nt], ah[mt], bl[nt]);
                    mma_tf32(acc[mt][nt], ah[mt], bh[nt]);
                }
        }
        __syncthreads();
    }

    // ---- epilogue: c0,c1 -> (row, col..col+1); c2,c3 -> (row+8, ...) ----
    #pragma unroll
    for (int mt = 0; mt < 4; mt++) {
        int r0 = blockIdx.y * 128 + wm * 64 + mt * 16 + gid;
        #pragma unroll
        for (int nt = 0; nt < NT; nt++) {
            int col = n0 + wn * WN + nt * 8 + tig * 2;
            float2 bv = bias ? *reinterpret_cast<const float2*>(bias + col)
                             : make_float2(0.f, 0.f);
            float2 o0 = make_float2(acc[mt][nt][0] + bv.x, acc[mt][nt][1] + bv.y);
            float2 o1 = make_float2(acc[mt][nt][2] + bv.x, acc[mt][nt][3] + bv.y);
            *reinterpret_cast<float2*>(Cb + (long long)r0 * ldc + col)       = o0;
            *reinterpret_cast<float2*>(Cb + (long long)(r0 + 8) * ldc + col) = o1;
        }
    }
}

// ---------------- spike gate ----------------------------------------------
__global__ void spike_kernel(const float* __restrict__ x,
                             const float* __restrict__ w_sur,
                             const float* __restrict__ b_sur,
                             const float* __restrict__ thr) {
    int row = blockIdx.x;
    const float4* xr = reinterpret_cast<const float4*>(x + (long long)row * Cn);
    const float4* wr = reinterpret_cast<const float4*>(w_sur);
    float s = 0.f;
    for (int i = threadIdx.x; i < Cn / 4; i += blockDim.x) {
        float4 a = xr[i], w = wr[i];
        s += a.x * w.x + a.y * w.y + a.z * w.z + a.w * w.w;
    }
    #pragma unroll
    for (int o = 16; o; o >>= 1) s += __shfl_xor_sync(0xffffffffu, s, o);
    __shared__ float smv[4];
    if ((threadIdx.x & 31) == 0) smv[threadIdx.x >> 5] = s;
    __syncthreads();
    if (threadIdx.x == 0) {
        float zz = smv[0] + smv[1] + smv[2] + smv[3] + b_sur[0];
        float imp = 1.f / (1.f + expf(-zz));
        g_spike[row] = (imp > thr[0]) ? 1.f : 0.f;
    }
}

// ---------------- expmap0 split + V repack --------------------------------
__global__ void expmap_kernel() {
    int wid  = (blockIdx.x * blockDim.x + threadIdx.x) >> 5;
    int lane = threadIdx.x & 31;
    if (wid >= BH * Tn) return;
    int bh = wid >> 10;
    int t  = wid & (Tn - 1);
    int b  = bh >> 4;
    int h  = bh & (Hn - 1);
    long long base = (long long)(b * Tn + t) * NQKV + h * Dn;
    const float* q = g_qkv + base;
    const float* k = q + Cn;
    const float* v = q + 2 * Cn;
    long long o = (long long)wid * Dn;
    {
        float u0v = q[lane], u1v = q[lane + 32];
        float ss = u0v * u0v + u1v * u1v;
        #pragma unroll
        for (int off = 16; off; off >>= 1) ss += __shfl_xor_sync(0xffffffffu, ss, off);
        float u0 = __shfl_sync(0xffffffffu, u0v, 0);
        float mink = ss - 2.f * u0 * u0;
        float nom  = sqrtf(fmaxf(mink, 1e-8f));
        float tq   = coshf(nom);
        float fac  = sinhf(nom) / nom;
        g_Lq[o + lane]      = (lane == 0) ? tq : fac * u0v;
        g_Lq[o + lane + 32] = fac * u1v;
    }
    {
        float u0v = k[lane], u1v = k[lane + 32];
        float ss = u0v * u0v + u1v * u1v;
        #pragma unroll
        for (int off = 16; off; off >>= 1) ss += __shfl_xor_sync(0xffffffffu, ss, off);
        float u0 = __shfl_sync(0xffffffffu, u0v, 0);
        float mink = ss - 2.f * u0 * u0;
        float nom  = sqrtf(fmaxf(mink, 1e-8f));
        float tk   = coshf(nom);
        float fac  = sinhf(nom) / nom;
        g_Lk[o + lane]      = (lane == 0) ? tk : -fac * u0v;
        g_Lk[o + lane + 32] = -fac * u1v;
    }
    g_V[o + lane]      = v[lane];
    g_V[o + lane + 32] = v[lane + 32];
}

// ---------------- scores: fp32 64-dot + acosh epilogue --------------------
__global__ void score_kernel() {
    int i0 = blockIdx.y * 64;
    int j0 = blockIdx.x * 64;
    int bh = blockIdx.z;
    if (j0 > i0 + 63) return;
    __shared__ float AqT[64][68];
    __shared__ float BkT[64][68];
    const float* Lq = g_Lq + (long long)bh * Tn * Dn;
    const float* Lk = g_Lk + (long long)bh * Tn * Dn;
    int tid = threadIdx.x;
    #pragma unroll
    for (int v = 0; v < 4; v++) {
        int f = tid + v * 256;
        int r = f >> 4;
        int c = (f & 15) * 4;
        float4 q4 = *reinterpret_cast<const float4*>(Lq + (long long)(i0 + r) * Dn + c);
        AqT[c + 0][r] = q4.x; AqT[c + 1][r] = q4.y; AqT[c + 2][r] = q4.z; AqT[c + 3][r] = q4.w;
        float4 k4 = *reinterpret_cast<const float4*>(Lk + (long long)(j0 + r) * Dn + c);
        BkT[c + 0][r] = k4.x; BkT[c + 1][r] = k4.y; BkT[c + 2][r] = k4.z; BkT[c + 3][r] = k4.w;
    }
    __syncthreads();
    int tx = tid & 15, ty = tid >> 4;
    float acc[4][4];
    #pragma unroll
    for (int i = 0; i < 4; i++)
        #pragma unroll
        for (int j = 0; j < 4; j++) acc[i][j] = 0.f;
    #pragma unroll 8
    for (int d = 0; d < 64; d++) {
        float af[4], bf[4];
        *reinterpret_cast<float4*>(af) = *reinterpret_cast<const float4*>(&AqT[d][ty * 4]);
        *reinterpret_cast<float4*>(bf) = *reinterpret_cast<const float4*>(&BkT[d][tx * 4]);
        #pragma unroll
        for (int i = 0; i < 4; i++)
            #pragma unroll
            for (int j = 0; j < 4; j++) acc[i][j] += af[i] * bf[j];
    }
    float* Sb = g_S + (long long)bh * Tn * Tn;
    #pragma unroll
    for (int ii = 0; ii < 4; ii++) {
        int i = i0 + ty * 4 + ii;
        #pragma unroll
        for (int jj = 0; jj < 4; jj++) {
            int j = j0 + tx * 4 + jj;
            float s;
            if (j > i) s = -INFINITY;
            else {
                float v = fmaxf(acc[ii][jj], 1.0f + 1e-7f);
                float dd = acoshf(v);
                s = -dd * dd * 0.125f;
            }
            Sb[(long long)i * Tn + j] = s;
        }
    }
}

// ---------------- causal softmax * spike(query) ---------------------------
__global__ void softmax_kernel() {
    int row = blockIdx.x;
    int i   = row & (Tn - 1);
    int bh  = row >> 10;
    int b   = bh >> 4;
    float spike = g_spike[b * Tn + i];
    float* S = g_S + (long long)row * Tn;
    int tid = threadIdx.x;
    if (spike == 0.f) {
        for (int j = tid; j < Tn; j += 128) S[j] = 0.f;
        return;
    }
    int nvalid = i + 1;
    float m = -INFINITY;
    for (int j = tid; j < nvalid; j += 128) m = fmaxf(m, S[j]);
    #pragma unroll
    for (int o = 16; o; o >>= 1) m = fmaxf(m, __shfl_xor_sync(0xffffffffu, m, o));
    __shared__ float smax[4], ssum[4];
    if ((tid & 31) == 0) smax[tid >> 5] = m;
    __syncthreads();
    m = fmaxf(fmaxf(smax[0], smax[1]), fmaxf(smax[2], smax[3]));
    float l = 0.f;
    for (int j = tid; j < nvalid; j += 128) l += expf(S[j] - m);
    #pragma unroll
    for (int o = 16; o; o >>= 1) l += __shfl_xor_sync(0xffffffffu, l, o);
    if ((tid & 31) == 0) ssum[tid >> 5] = l;
    __syncthreads();
    l = ssum[0] + ssum[1] + ssum[2] + ssum[3];
    float inv = 1.f / l;
    for (int j = tid; j < Tn; j += 128) {
        float p = (j < nvalid) ? expf(S[j] - m) * inv : 0.f;
        S[j] = p;
    }
}

// ---------------- launch ---------------------------------------------------
extern "C" void kernel_launch(void* const* d_in, const int* in_sizes, int n_in,
                              void* d_out, int out_size) {
    const float* x     = (const float*)d_in[0];
    const float* W_qkv = (const float*)d_in[1];
    const float* b_qkv = (const float*)d_in[2];
    const float* W_out = (const float*)d_in[3];
    const float* b_out = (const float*)d_in[4];
    const float* w_sur = (const float*)d_in[5];
    const float* b_sur = (const float*)d_in[6];
    const float* thr   = (const float*)d_in[7];
    float* out = (float*)d_out;

    float *p_qkv, *p_S, *p_V, *p_y;
    cudaGetSymbolAddress((void**)&p_qkv, g_qkv);
    cudaGetSymbolAddress((void**)&p_S,   g_S);
    cudaGetSymbolAddress((void**)&p_V,   g_V);
    cudaGetSymbolAddress((void**)&p_y,   g_y);

    // dynamic smem: 2 stages of (A 128x36 + B 32x(BN+4)) floats
    const int smem128 = (2 * 128 * 36 + 2 * 32 * 132) * 4;  // 70656
    const int smem64  = (2 * 128 * 36 + 2 * 32 * 68)  * 4;  // 54272
    cudaFuncSetAttribute(mma_gemm<128>, cudaFuncAttributeMaxDynamicSharedMemorySize, smem128);
    cudaFuncSetAttribute(mma_gemm<64>,  cudaFuncAttributeMaxDynamicSharedMemorySize, smem64);

    // 1) spike gate
    spike_kernel<<<BT, 128>>>(x, w_sur, b_sur, thr);

    // 2) QKV GEMM: (4096x1024)@(1024x3072)+b   [tf32 3x tensor cores]
    mma_gemm<128><<<dim3(NQKV / 128, BT / 128, 1), 256, smem128>>>(
        x, Cn, 0, W_qkv, NQKV, 0,
        p_qkv, NQKV, 1, 0, 0, Cn, b_qkv);

    // 3) expmap + V repack
    expmap_kernel<<<(BH * Tn) / 8, 256>>>();

    // 4) scores (fp32)
    score_kernel<<<dim3(16, 16, BH), 256>>>();

    // 5) softmax
    softmax_kernel<<<BH * Tn, 128>>>();

    // 6) P@V batched: per bh (1024x1024)@(1024x64)
    mma_gemm<64><<<dim3(1, Tn / 128, BH), 256, smem64>>>(
        p_S, Tn, (long long)Tn * Tn, p_V, Dn, (long long)Tn * Dn,
        p_y, Cn, Hn, (long long)Tn * Cn, Dn,
        Tn, nullptr);

    // 7) output GEMM: (4096x1024)@(1024x1024)+b
    mma_gemm<128><<<dim3(Cn / 128, BT / 128, 1), 256, smem128>>>(
        p_y, Cn, 0, W_out, Cn, 0,
        out, Cn, 1, 0, 0, Cn, b_out);
}

// round 6
// speedup vs baseline: 1.5913x; 1.1497x over previous
#include <cuda_runtime.h>
#include <math.h>
#include <stdint.h>

// Problem constants
#define Bn 4
#define Tn 1024
#define Cn 1024
#define Hn 16
#define Dn 64
constexpr int BT   = Bn * Tn;          // 4096
constexpr int BH   = Bn * Hn;          // 64
constexpr int NQKV = 3 * Cn;           // 3072

// ---------------- scratch (static device allocations) ---------------------
__device__ float g_qkv[BT * NQKV];            // 48 MB
__device__ float g_Lq [BH * Tn * Dn];         // 16 MB
__device__ float g_Lk [BH * Tn * Dn];
__device__ float g_V  [BH * Tn * Dn];
__device__ float g_y  [BT * Cn];              // 16 MB
__device__ float g_spike[BT];
__device__ int   g_idx[BT];                   // compacted spiking t per batch
__device__ int   g_cnt[Bn];

// ======================= helpers ==========================================
__device__ __forceinline__ uint32_t smem_u32(const void* p) {
    uint32_t a;
    asm("{ .reg .u64 t; cvta.to.shared.u64 t, %1; cvt.u32.u64 %0, t; }" : "=r"(a) : "l"(p));
    return a;
}
__device__ __forceinline__ uint32_t cvt_tf32(float x) {
    uint32_t r; asm("cvt.rna.tf32.f32 %0, %1;" : "=r"(r) : "f"(x)); return r;
}
__device__ __forceinline__ void mma_tf32(float* c, const uint32_t* a, const uint32_t* b) {
    asm volatile(
        "mma.sync.aligned.m16n8k8.row.col.f32.tf32.tf32.f32 "
        "{%0,%1,%2,%3}, {%4,%5,%6,%7}, {%8,%9}, {%0,%1,%2,%3};"
        : "+f"(c[0]), "+f"(c[1]), "+f"(c[2]), "+f"(c[3])
        : "r"(a[0]), "r"(a[1]), "r"(a[2]), "r"(a[3]), "r"(b[0]), "r"(b[1]));
}
__device__ __forceinline__ void cp_async16(uint32_t dst, const void* src) {
    asm volatile("cp.async.cg.shared.global [%0], [%1], 16;" :: "r"(dst), "l"(src));
}

// ======================= tf32 3x mma.sync GEMM (dense) =====================
template<int BN>
__global__ __launch_bounds__(256, 1)
void mma_gemm(const float* __restrict__ A, int lda, long long sAz,
              const float* __restrict__ Bg, int ldb, long long sBz,
              float* __restrict__ Cm, int ldc,
              int cdiv, long long sC_hi, long long sC_lo,
              int K, const float* __restrict__ bias) {
    constexpr int SA   = 36;
    constexpr int SB   = BN + 4;
    constexpr int A_EL = 128 * SA;
    constexpr int B_EL = 32 * SB;
    constexpr int WN   = BN / 4;
    constexpr int NT   = WN / 8;
    constexpr int BSEG = BN / 4;

    extern __shared__ float sm[];
    float* smA = sm;
    float* smB = sm + 2 * A_EL;
    uint32_t smA_u = smem_u32(smA);
    uint32_t smB_u = smem_u32(smB);

    const int tid  = threadIdx.x;
    const int lane = tid & 31;
    const int wid  = tid >> 5;
    const int wm   = wid & 1;
    const int wn   = wid >> 1;
    const int gid  = lane >> 2;
    const int tig  = lane & 3;

    const int z  = blockIdx.z;
    const int n0 = blockIdx.x * BN;
    const float* Ab = A  + (long long)z * sAz + (long long)blockIdx.y * 128 * lda;
    const float* Bb = Bg + (long long)z * sBz;
    float*       Cb = Cm + (long long)(z / cdiv) * sC_hi + (long long)(z % cdiv) * sC_lo;

    const int NC = K >> 5;

    float acc[4][NT][4];
    #pragma unroll
    for (int mt = 0; mt < 4; mt++)
        #pragma unroll
        for (int nt = 0; nt < NT; nt++)
            #pragma unroll
            for (int i = 0; i < 4; i++) acc[mt][nt][i] = 0.f;

    auto load_chunk = [&](int c, int st) {
        #pragma unroll
        for (int j = 0; j < 4; j++) {
            int idx = tid + j * 256;
            int r = idx >> 3, s = idx & 7;
            cp_async16(smA_u + (uint32_t)((st * A_EL + r * SA + s * 4) << 2),
                       Ab + (long long)r * lda + c * 32 + s * 4);
        }
        #pragma unroll
        for (int j = 0; j < (32 * BSEG) / 256; j++) {
            int idx = tid + j * 256;
            int r = idx / BSEG, s = idx % BSEG;
            cp_async16(smB_u + (uint32_t)((st * B_EL + r * SB + s * 4) << 2),
                       Bb + (long long)(c * 32 + r) * ldb + n0 + s * 4);
        }
        asm volatile("cp.async.commit_group;" ::: "memory");
    };

    load_chunk(0, 0);
    for (int c = 0; c < NC; c++) {
        const int st = c & 1;
        if (c + 1 < NC) {
            load_chunk(c + 1, st ^ 1);
            asm volatile("cp.async.wait_group 1;" ::: "memory");
        } else {
            asm volatile("cp.async.wait_group 0;" ::: "memory");
        }
        __syncthreads();

        const float* cA = smA + st * A_EL;
        const float* cB = smB + st * B_EL;
        #pragma unroll
        for (int ks = 0; ks < 4; ks++) {
            const int k0 = ks * 8;
            uint32_t ah[4][4], al[4][4];
            #pragma unroll
            for (int mt = 0; mt < 4; mt++) {
                const float* p = cA + (wm * 64 + mt * 16 + gid) * SA + k0 + tig;
                float a0 = p[0], a1 = p[8 * SA], a2 = p[4], a3 = p[8 * SA + 4];
                ah[mt][0] = cvt_tf32(a0); al[mt][0] = cvt_tf32(a0 - __uint_as_float(ah[mt][0]));
                ah[mt][1] = cvt_tf32(a1); al[mt][1] = cvt_tf32(a1 - __uint_as_float(ah[mt][1]));
                ah[mt][2] = cvt_tf32(a2); al[mt][2] = cvt_tf32(a2 - __uint_as_float(ah[mt][2]));
                ah[mt][3] = cvt_tf32(a3); al[mt][3] = cvt_tf32(a3 - __uint_as_float(ah[mt][3]));
            }
            uint32_t bh[NT][2], bl[NT][2];
            #pragma unroll
            for (int nt = 0; nt < NT; nt++) {
                const float* p = cB + (k0 + tig) * SB + wn * WN + nt * 8 + gid;
                float b0 = p[0], b1 = p[4 * SB];
                bh[nt][0] = cvt_tf32(b0); bl[nt][0] = cvt_tf32(b0 - __uint_as_float(bh[nt][0]));
                bh[nt][1] = cvt_tf32(b1); bl[nt][1] = cvt_tf32(b1 - __uint_as_float(bh[nt][1]));
            }
            #pragma unroll
            for (int mt = 0; mt < 4; mt++)
                #pragma unroll
                for (int nt = 0; nt < NT; nt++) {
                    mma_tf32(acc[mt][nt], al[mt], bh[nt]);
                    mma_tf32(acc[mt][nt], ah[mt], bl[nt]);
                    mma_tf32(acc[mt][nt], ah[mt], bh[nt]);
                }
        }
        __syncthreads();
    }

    #pragma unroll
    for (int mt = 0; mt < 4; mt++) {
        int r0 = blockIdx.y * 128 + wm * 64 + mt * 16 + gid;
        #pragma unroll
        for (int nt = 0; nt < NT; nt++) {
            int col = n0 + wn * WN + nt * 8 + tig * 2;
            float2 bv = bias ? *reinterpret_cast<const float2*>(bias + col)
                             : make_float2(0.f, 0.f);
            float2 o0 = make_float2(acc[mt][nt][0] + bv.x, acc[mt][nt][1] + bv.y);
            float2 o1 = make_float2(acc[mt][nt][2] + bv.x, acc[mt][nt][3] + bv.y);
            *reinterpret_cast<float2*>(Cb + (long long)r0 * ldc + col)       = o0;
            *reinterpret_cast<float2*>(Cb + (long long)(r0 + 8) * ldc + col) = o1;
        }
    }
}

// ---------------- spike gate ----------------------------------------------
__global__ void spike_kernel(const float* __restrict__ x,
                             const float* __restrict__ w_sur,
                             const float* __restrict__ b_sur,
                             const float* __restrict__ thr) {
    int row = blockIdx.x;
    const float4* xr = reinterpret_cast<const float4*>(x + (long long)row * Cn);
    const float4* wr = reinterpret_cast<const float4*>(w_sur);
    float s = 0.f;
    for (int i = threadIdx.x; i < Cn / 4; i += blockDim.x) {
        float4 a = xr[i], w = wr[i];
        s += a.x * w.x + a.y * w.y + a.z * w.z + a.w * w.w;
    }
    #pragma unroll
    for (int o = 16; o; o >>= 1) s += __shfl_xor_sync(0xffffffffu, s, o);
    __shared__ float smv[4];
    if ((threadIdx.x & 31) == 0) smv[threadIdx.x >> 5] = s;
    __syncthreads();
    if (threadIdx.x == 0) {
        float zz = smv[0] + smv[1] + smv[2] + smv[3] + b_sur[0];
        float imp = 1.f / (1.f + expf(-zz));
        g_spike[row] = (imp > thr[0]) ? 1.f : 0.f;
    }
}

// ---------------- compact spiking query indices per batch -----------------
__global__ void compact_kernel() {      // grid Bn, block 1024
    int b = blockIdx.x, t = threadIdx.x;
    __shared__ int pre[Tn];
    int s = (g_spike[b * Tn + t] > 0.f) ? 1 : 0;
    pre[t] = s;
    __syncthreads();
    for (int off = 1; off < Tn; off <<= 1) {
        int v = (t >= off) ? pre[t - off] : 0;
        __syncthreads();
        pre[t] += v;
        __syncthreads();
    }
    if (s) g_idx[b * Tn + pre[t] - 1] = t;
    if (t == Tn - 1) g_cnt[b] = pre[Tn - 1];
}

// ---------------- expmap0 split + V repack --------------------------------
__global__ void expmap_kernel() {
    int wid  = (blockIdx.x * blockDim.x + threadIdx.x) >> 5;
    int lane = threadIdx.x & 31;
    if (wid >= BH * Tn) return;
    int bh = wid >> 10;
    int t  = wid & (Tn - 1);
    int b  = bh >> 4;
    int h  = bh & (Hn - 1);
    long long base = (long long)(b * Tn + t) * NQKV + h * Dn;
    const float* q = g_qkv + base;
    const float* k = q + Cn;
    const float* v = q + 2 * Cn;
    long long o = (long long)wid * Dn;
    {
        float u0v = q[lane], u1v = q[lane + 32];
        float ss = u0v * u0v + u1v * u1v;
        #pragma unroll
        for (int off = 16; off; off >>= 1) ss += __shfl_xor_sync(0xffffffffu, ss, off);
        float u0 = __shfl_sync(0xffffffffu, u0v, 0);
        float mink = ss - 2.f * u0 * u0;
        float nom  = sqrtf(fmaxf(mink, 1e-8f));
        float tq   = coshf(nom);
        float fac  = sinhf(nom) / nom;
        g_Lq[o + lane]      = (lane == 0) ? tq : fac * u0v;
        g_Lq[o + lane + 32] = fac * u1v;
    }
    {
        float u0v = k[lane], u1v = k[lane + 32];
        float ss = u0v * u0v + u1v * u1v;
        #pragma unroll
        for (int off = 16; off; off >>= 1) ss += __shfl_xor_sync(0xffffffffu, ss, off);
        float u0 = __shfl_sync(0xffffffffu, u0v, 0);
        float mink = ss - 2.f * u0 * u0;
        float nom  = sqrtf(fmaxf(mink, 1e-8f));
        float tk   = coshf(nom);
        float fac  = sinhf(nom) / nom;
        g_Lk[o + lane]      = (lane == 0) ? tk : -fac * u0v;
        g_Lk[o + lane + 32] = -fac * u1v;
    }
    g_V[o + lane]      = v[lane];
    g_V[o + lane + 32] = v[lane + 32];
}

// ================= fused flash attention (compacted spiking queries) =======
// grid (8, BH), 256 threads / 8 warps; each warp owns 16 query rows.
__global__ __launch_bounds__(256, 1)
void flash_kernel() {
    const int bh = blockIdx.y;
    const int b  = bh >> 4;
    const int h  = bh & (Hn - 1);
    const int qt = blockIdx.x;
    const int nb = g_cnt[b];
    if (qt * 128 >= nb) return;

    extern __shared__ float fs[];
    float* sQ = fs;                        // 128 x 68
    float* sK = sQ + 128 * 68;             // 2 x 64 x 68
    float* sV = sK + 2 * 64 * 68;          // 2 x 64 x 68
    float* sP = sV + 2 * 64 * 68;          // 128 x 68
    int*   sT = (int*)(sP + 128 * 68);     // 128
    uint32_t uQ = smem_u32(sQ), uK = smem_u32(sK), uV = smem_u32(sV);

    const int tid  = threadIdx.x;
    const int lane = tid & 31;
    const int w    = tid >> 5;
    const int gid  = lane >> 2;
    const int tig  = lane & 3;

    if (tid < 128) {
        int ip = qt * 128 + tid;
        sT[tid] = (ip < nb) ? g_idx[b * Tn + ip] : -1;
    }
    __syncthreads();

    const int ilast = min(nb - 1, qt * 128 + 127);
    const int jmax  = g_idx[b * Tn + ilast];
    const int nj    = (jmax >> 6) + 1;

    const float* Lqb = g_Lq + (long long)bh * Tn * Dn;
    const float* Lkb = g_Lk + (long long)bh * Tn * Dn;
    const float* Vb  = g_V  + (long long)bh * Tn * Dn;

    // gather Q rows (group together with tile-0 K/V)
    #pragma unroll
    for (int i = 0; i < 8; i++) {
        int f4 = tid + i * 256;
        int r = f4 >> 4, s = f4 & 15;
        int t = sT[r]; if (t < 0) t = 0;
        cp_async16(uQ + (uint32_t)((r * 68 + s * 4) << 2), Lqb + (long long)t * 64 + s * 4);
    }
    auto loadKV = [&](int jt, int st) {
        #pragma unroll
        for (int i = 0; i < 4; i++) {
            int f4 = tid + i * 256;
            int r = f4 >> 4, s = f4 & 15;
            long long src = (long long)(jt * 64 + r) * 64 + s * 4;
            uint32_t off = (uint32_t)((st * 64 * 68 + r * 68 + s * 4) << 2);
            cp_async16(uK + off, Lkb + src);
            cp_async16(uV + off, Vb + src);
        }
        asm volatile("cp.async.commit_group;" ::: "memory");
    };
    loadKV(0, 0);

    const int t0 = sT[w * 16 + gid];
    const int t1 = sT[w * 16 + gid + 8];

    float m0 = -INFINITY, m1 = -INFINITY, l0 = 0.f, l1 = 0.f;
    float yacc[8][4];
    #pragma unroll
    for (int nt = 0; nt < 8; nt++)
        #pragma unroll
        for (int i = 0; i < 4; i++) yacc[nt][i] = 0.f;

    for (int jt = 0; jt < nj; jt++) {
        const int st = jt & 1;
        const int j0 = jt * 64;
        if (jt > 0) __syncthreads();
        if (jt + 1 < nj) {
            loadKV(jt + 1, st ^ 1);
            asm volatile("cp.async.wait_group 1;" ::: "memory");
        } else {
            asm volatile("cp.async.wait_group 0;" ::: "memory");
        }
        __syncthreads();

        const float* cK = sK + st * 64 * 68;
        const float* cV = sV + st * 64 * 68;

        // ---- S tile = Lq . Lk^T  (tf32 3x) ----
        float sacc[8][4];
        #pragma unroll
        for (int nt = 0; nt < 8; nt++)
            #pragma unroll
            for (int i = 0; i < 4; i++) sacc[nt][i] = 0.f;

        #pragma unroll
        for (int ks = 0; ks < 8; ks++) {
            const int k0 = ks * 8;
            const float* pA = sQ + (w * 16 + gid) * 68 + k0 + tig;
            float a0 = pA[0], a1 = pA[8 * 68], a2 = pA[4], a3 = pA[8 * 68 + 4];
            uint32_t ah[4], al[4];
            ah[0] = cvt_tf32(a0); al[0] = cvt_tf32(a0 - __uint_as_float(ah[0]));
            ah[1] = cvt_tf32(a1); al[1] = cvt_tf32(a1 - __uint_as_float(ah[1]));
            ah[2] = cvt_tf32(a2); al[2] = cvt_tf32(a2 - __uint_as_float(ah[2]));
            ah[3] = cvt_tf32(a3); al[3] = cvt_tf32(a3 - __uint_as_float(ah[3]));
            #pragma unroll
            for (int nt = 0; nt < 8; nt++) {
                const float* pB = cK + (nt * 8 + gid) * 68 + k0 + tig;
                float b0 = pB[0], b1 = pB[4];
                uint32_t bh2[2], bl2[2];
                bh2[0] = cvt_tf32(b0); bl2[0] = cvt_tf32(b0 - __uint_as_float(bh2[0]));
                bh2[1] = cvt_tf32(b1); bl2[1] = cvt_tf32(b1 - __uint_as_float(bh2[1]));
                mma_tf32(sacc[nt], al, bh2);
                mma_tf32(sacc[nt], ah, bl2);
                mma_tf32(sacc[nt], ah, bh2);
            }
        }

        // ---- epilogue: acosh score + online softmax ----
        float mx0 = -INFINITY, mx1 = -INFINITY;
        #pragma unroll
        for (int nt = 0; nt < 8; nt++) {
            #pragma unroll
            for (int e = 0; e < 4; e++) {
                int j  = j0 + nt * 8 + 2 * tig + (e & 1);
                int tr = (e < 2) ? t0 : t1;
                float s;
                if (j > tr) s = -INFINITY;
                else {
                    float v = fmaxf(sacc[nt][e], 1.0f + 1e-7f);
                    float dd = acoshf(v);
                    s = -dd * dd * 0.125f;
                }
                sacc[nt][e] = s;
                if (e < 2) mx0 = fmaxf(mx0, s); else mx1 = fmaxf(mx1, s);
            }
        }
        mx0 = fmaxf(mx0, __shfl_xor_sync(0xffffffffu, mx0, 1));
        mx0 = fmaxf(mx0, __shfl_xor_sync(0xffffffffu, mx0, 2));
        mx1 = fmaxf(mx1, __shfl_xor_sync(0xffffffffu, mx1, 1));
        mx1 = fmaxf(mx1, __shfl_xor_sync(0xffffffffu, mx1, 2));
        float mn0 = fmaxf(m0, mx0), mn1 = fmaxf(m1, mx1);
        float al0 = (mn0 == -INFINITY) ? 0.f : expf(m0 - mn0);
        float al1 = (mn1 == -INFINITY) ? 0.f : expf(m1 - mn1);
        m0 = mn0; m1 = mn1;

        float ps0 = 0.f, ps1 = 0.f;
        float* pr0 = sP + (w * 16 + gid) * 68;
        float* pr1 = sP + (w * 16 + gid + 8) * 68;
        #pragma unroll
        for (int nt = 0; nt < 8; nt++) {
            int cc = nt * 8 + 2 * tig;
            float p0 = (mn0 == -INFINITY) ? 0.f : expf(sacc[nt][0] - mn0);
            float p1 = (mn0 == -INFINITY) ? 0.f : expf(sacc[nt][1] - mn0);
            float p2 = (mn1 == -INFINITY) ? 0.f : expf(sacc[nt][2] - mn1);
            float p3 = (mn1 == -INFINITY) ? 0.f : expf(sacc[nt][3] - mn1);
            *reinterpret_cast<float2*>(pr0 + cc) = make_float2(p0, p1);
            *reinterpret_cast<float2*>(pr1 + cc) = make_float2(p2, p3);
            ps0 += p0 + p1; ps1 += p2 + p3;
        }
        l0 = l0 * al0 + ps0;
        l1 = l1 * al1 + ps1;
        #pragma unroll
        for (int nt = 0; nt < 8; nt++) {
            yacc[nt][0] *= al0; yacc[nt][1] *= al0;
            yacc[nt][2] *= al1; yacc[nt][3] *= al1;
        }
        __syncwarp();

        // ---- y += P . V  (tf32 3-term) ----
        #pragma unroll
        for (int ks = 0; ks < 8; ks++) {
            const int k0 = ks * 8;
            const float* pA = sP + (w * 16 + gid) * 68 + k0 + tig;
            float a0 = pA[0], a1 = pA[8 * 68], a2 = pA[4], a3 = pA[8 * 68 + 4];
            uint32_t ah[4], al[4];
            ah[0] = cvt_tf32(a0); al[0] = cvt_tf32(a0 - __uint_as_float(ah[0]));
            ah[1] = cvt_tf32(a1); al[1] = cvt_tf32(a1 - __uint_as_float(ah[1]));
            ah[2] = cvt_tf32(a2); al[2] = cvt_tf32(a2 - __uint_as_float(ah[2]));
            ah[3] = cvt_tf32(a3); al[3] = cvt_tf32(a3 - __uint_as_float(ah[3]));
            #pragma unroll
            for (int nt = 0; nt < 8; nt++) {
                const float* pB = cV + (k0 + tig) * 68 + nt * 8 + gid;
                float b0 = pB[0], b1 = pB[4 * 68];
                uint32_t bh2[2], bl2[2];
                bh2[0] = cvt_tf32(b0); bl2[0] = cvt_tf32(b0 - __uint_as_float(bh2[0]));
                bh2[1] = cvt_tf32(b1); bl2[1] = cvt_tf32(b1 - __uint_as_float(bh2[1]));
                mma_tf32(yacc[nt], al, bh2);
                mma_tf32(yacc[nt], ah, bl2);
                mma_tf32(yacc[nt], ah, bh2);
            }
        }
        __syncwarp();
    }

    // ---- finalize: divide by l, scatter to g_y ----
    l0 += __shfl_xor_sync(0xffffffffu, l0, 1);
    l0 += __shfl_xor_sync(0xffffffffu, l0, 2);
    l1 += __shfl_xor_sync(0xffffffffu, l1, 1);
    l1 += __shfl_xor_sync(0xffffffffu, l1, 2);
    float inv0 = 1.f / l0, inv1 = 1.f / l1;
    #pragma unroll
    for (int nt = 0; nt < 8; nt++) {
        int col = h * 64 + nt * 8 + 2 * tig;
        if (t0 >= 0)
            *reinterpret_cast<float2*>(g_y + (long long)(b * Tn + t0) * Cn + col)
                = make_float2(yacc[nt][0] * inv0, yacc[nt][1] * inv0);
        if (t1 >= 0)
            *reinterpret_cast<float2*>(g_y + (long long)(b * Tn + t1) * Cn + col)
                = make_float2(yacc[nt][2] * inv1, yacc[nt][3] * inv1);
    }
}

// ---------------- launch ---------------------------------------------------
extern "C" void kernel_launch(void* const* d_in, const int* in_sizes, int n_in,
                              void* d_out, int out_size) {
    const float* x     = (const float*)d_in[0];
    const float* W_qkv = (const float*)d_in[1];
    const float* b_qkv = (const float*)d_in[2];
    const float* W_out = (const float*)d_in[3];
    const float* b_out = (const float*)d_in[4];
    const float* w_sur = (const float*)d_in[5];
    const float* b_sur = (const float*)d_in[6];
    const float* thr   = (const float*)d_in[7];
    float* out = (float*)d_out;

    float *p_qkv, *p_y;
    cudaGetSymbolAddress((void**)&p_qkv, g_qkv);
    cudaGetSymbolAddress((void**)&p_y,   g_y);

    const int smem128 = (2 * 128 * 36 + 2 * 32 * 132) * 4;  // 70656
    const int smemFl  = (128 * 68 + 4 * 64 * 68 + 128 * 68) * 4 + 512;  // ~140KB
    cudaFuncSetAttribute(mma_gemm<128>, cudaFuncAttributeMaxDynamicSharedMemorySize, smem128);
    cudaFuncSetAttribute(flash_kernel,  cudaFuncAttributeMaxDynamicSharedMemorySize, smemFl);

    // 1) spike gate + compaction
    spike_kernel<<<BT, 128>>>(x, w_sur, b_sur, thr);
    compact_kernel<<<Bn, Tn>>>();

    // 2) QKV GEMM (tf32 3x)
    mma_gemm<128><<<dim3(NQKV / 128, BT / 128, 1), 256, smem128>>>(
        x, Cn, 0, W_qkv, NQKV, 0,
        p_qkv, NQKV, 1, 0, 0, Cn, b_qkv);

    // 3) expmap + V repack
    expmap_kernel<<<(BH * Tn) / 8, 256>>>();

    // 4) zero y (non-spiking rows stay zero)
    cudaMemsetAsync(p_y, 0, (size_t)BT * Cn * sizeof(float));

    // 5) fused attention over compacted spiking queries
    flash_kernel<<<dim3(Tn / 128, BH), 256, smemFl>>>();

    // 6) output GEMM (tf32 3x)
    mma_gemm<128><<<dim3(Cn / 128, BT / 128, 1), 256, smem128>>>(
        p_y, Cn, 0, W_out, Cn, 0,
        out, Cn, 1, 0, 0, Cn, b_out);
}

// round 7
// speedup vs baseline: 1.8144x; 1.1402x over previous
#include <cuda_runtime.h>
#include <cuda_bf16.h>
#include <math.h>
#include <stdint.h>

// Problem constants
#define Bn 4
#define Tn 1024
#define Cn 1024
#define Hn 16
#define Dn 64
constexpr int BT   = Bn * Tn;          // 4096
constexpr int BH   = Bn * Hn;          // 64
constexpr int NQKV = 3 * Cn;           // 3072

// ---------------- scratch (static device allocations) ---------------------
__device__ float g_qkv[BT * NQKV];            // 48 MB
__device__ float g_Lq [BH * Tn * Dn];         // 16 MB
__device__ float g_Lk [BH * Tn * Dn];
__device__ float g_V  [BH * Tn * Dn];
__device__ float g_y  [BT * Cn];              // 16 MB
__device__ float g_spike[BT];
__device__ int   g_idx[BT];                   // compacted spiking t per batch
__device__ int   g_cnt[Bn];

// ======================= helpers ==========================================
__device__ __forceinline__ uint32_t smem_u32(const void* p) {
    uint32_t a;
    asm("{ .reg .u64 t; cvta.to.shared.u64 t, %1; cvt.u32.u64 %0, t; }" : "=r"(a) : "l"(p));
    return a;
}
__device__ __forceinline__ uint32_t cvt_tf32(float x) {
    uint32_t r; asm("cvt.rna.tf32.f32 %0, %1;" : "=r"(r) : "f"(x)); return r;
}
__device__ __forceinline__ void mma_tf32(float* c, const uint32_t* a, const uint32_t* b) {
    asm volatile(
        "mma.sync.aligned.m16n8k8.row.col.f32.tf32.tf32.f32 "
        "{%0,%1,%2,%3}, {%4,%5,%6,%7}, {%8,%9}, {%0,%1,%2,%3};"
        : "+f"(c[0]), "+f"(c[1]), "+f"(c[2]), "+f"(c[3])
        : "r"(a[0]), "r"(a[1]), "r"(a[2]), "r"(a[3]), "r"(b[0]), "r"(b[1]));
}
__device__ __forceinline__ void mma_bf16(float* c, const uint32_t* a, const uint32_t* b) {
    asm volatile(
        "mma.sync.aligned.m16n8k16.row.col.f32.bf16.bf16.f32 "
        "{%0,%1,%2,%3}, {%4,%5,%6,%7}, {%8,%9}, {%0,%1,%2,%3};"
        : "+f"(c[0]), "+f"(c[1]), "+f"(c[2]), "+f"(c[3])
        : "r"(a[0]), "r"(a[1]), "r"(a[2]), "r"(a[3]), "r"(b[0]), "r"(b[1]));
}
// pack (x,y) into bf16x2 (x in low half) + residual plane
__device__ __forceinline__ void split2(float x, float y, uint32_t& h, uint32_t& l) {
    __nv_bfloat162 t = __floats2bfloat162_rn(x, y);
    uint32_t u = *reinterpret_cast<uint32_t*>(&t);
    h = u;
    float lx = x - __uint_as_float(u << 16);
    float ly = y - __uint_as_float(u & 0xFFFF0000u);
    __nv_bfloat162 t2 = __floats2bfloat162_rn(lx, ly);
    l = *reinterpret_cast<uint32_t*>(&t2);
}
__device__ __forceinline__ void cp_async16(uint32_t dst, const void* src) {
    asm volatile("cp.async.cg.shared.global [%0], [%1], 16;" :: "r"(dst), "l"(src));
}

// ======================= tf32 3x mma.sync GEMM (QKV) =======================
template<int BN>
__global__ __launch_bounds__(256, 1)
void mma_gemm(const float* __restrict__ A, int lda,
              const float* __restrict__ Bg, int ldb,
              float* __restrict__ Cm, int ldc,
              int K, const float* __restrict__ bias) {
    constexpr int SA   = 36;
    constexpr int SB   = BN + 4;
    constexpr int A_EL = 128 * SA;
    constexpr int B_EL = 32 * SB;
    constexpr int WN   = BN / 4;
    constexpr int NT   = WN / 8;
    constexpr int BSEG = BN / 4;

    extern __shared__ float sm[];
    float* smA = sm;
    float* smB = sm + 2 * A_EL;
    uint32_t smA_u = smem_u32(smA);
    uint32_t smB_u = smem_u32(smB);

    const int tid  = threadIdx.x;
    const int lane = tid & 31;
    const int wid  = tid >> 5;
    const int wm   = wid & 1;
    const int wn   = wid >> 1;
    const int gid  = lane >> 2;
    const int tig  = lane & 3;

    const int n0 = blockIdx.x * BN;
    const float* Ab = A + (long long)blockIdx.y * 128 * lda;
    const float* Bb = Bg;
    float*       Cb = Cm;

    const int NC = K >> 5;

    float acc[4][NT][4];
    #pragma unroll
    for (int mt = 0; mt < 4; mt++)
        #pragma unroll
        for (int nt = 0; nt < NT; nt++)
            #pragma unroll
            for (int i = 0; i < 4; i++) acc[mt][nt][i] = 0.f;

    auto load_chunk = [&](int c, int st) {
        #pragma unroll
        for (int j = 0; j < 4; j++) {
            int idx = tid + j * 256;
            int r = idx >> 3, s = idx & 7;
            cp_async16(smA_u + (uint32_t)((st * A_EL + r * SA + s * 4) << 2),
                       Ab + (long long)r * lda + c * 32 + s * 4);
        }
        #pragma unroll
        for (int j = 0; j < (32 * BSEG) / 256; j++) {
            int idx = tid + j * 256;
            int r = idx / BSEG, s = idx % BSEG;
            cp_async16(smB_u + (uint32_t)((st * B_EL + r * SB + s * 4) << 2),
                       Bb + (long long)(c * 32 + r) * ldb + n0 + s * 4);
        }
        asm volatile("cp.async.commit_group;" ::: "memory");
    };

    load_chunk(0, 0);
    for (int c = 0; c < NC; c++) {
        const int st = c & 1;
        if (c + 1 < NC) {
            load_chunk(c + 1, st ^ 1);
            asm volatile("cp.async.wait_group 1;" ::: "memory");
        } else {
            asm volatile("cp.async.wait_group 0;" ::: "memory");
        }
        __syncthreads();

        const float* cA = smA + st * A_EL;
        const float* cB = smB + st * B_EL;
        #pragma unroll
        for (int ks = 0; ks < 4; ks++) {
            const int k0 = ks * 8;
            uint32_t ah[4][4], al[4][4];
            #pragma unroll
            for (int mt = 0; mt < 4; mt++) {
                const float* p = cA + (wm * 64 + mt * 16 + gid) * SA + k0 + tig;
                float a0 = p[0], a1 = p[8 * SA], a2 = p[4], a3 = p[8 * SA + 4];
                ah[mt][0] = cvt_tf32(a0); al[mt][0] = cvt_tf32(a0 - __uint_as_float(ah[mt][0]));
                ah[mt][1] = cvt_tf32(a1); al[mt][1] = cvt_tf32(a1 - __uint_as_float(ah[mt][1]));
                ah[mt][2] = cvt_tf32(a2); al[mt][2] = cvt_tf32(a2 - __uint_as_float(ah[mt][2]));
                ah[mt][3] = cvt_tf32(a3); al[mt][3] = cvt_tf32(a3 - __uint_as_float(ah[mt][3]));
            }
            uint32_t bh[NT][2], bl[NT][2];
            #pragma unroll
            for (int nt = 0; nt < NT; nt++) {
                const float* p = cB + (k0 + tig) * SB + wn * WN + nt * 8 + gid;
                float b0 = p[0], b1 = p[4 * SB];
                bh[nt][0] = cvt_tf32(b0); bl[nt][0] = cvt_tf32(b0 - __uint_as_float(bh[nt][0]));
                bh[nt][1] = cvt_tf32(b1); bl[nt][1] = cvt_tf32(b1 - __uint_as_float(bh[nt][1]));
            }
            #pragma unroll
            for (int mt = 0; mt < 4; mt++)
                #pragma unroll
                for (int nt = 0; nt < NT; nt++) {
                    mma_tf32(acc[mt][nt], al[mt], bh[nt]);
                    mma_tf32(acc[mt][nt], ah[mt], bl[nt]);
                    mma_tf32(acc[mt][nt], ah[mt], bh[nt]);
                }
        }
        __syncthreads();
    }

    #pragma unroll
    for (int mt = 0; mt < 4; mt++) {
        int r0 = blockIdx.y * 128 + wm * 64 + mt * 16 + gid;
        #pragma unroll
        for (int nt = 0; nt < NT; nt++) {
            int col = n0 + wn * WN + nt * 8 + tig * 2;
            float2 bv = bias ? *reinterpret_cast<const float2*>(bias + col)
                             : make_float2(0.f, 0.f);
            float2 o0 = make_float2(acc[mt][nt][0] + bv.x, acc[mt][nt][1] + bv.y);
            float2 o1 = make_float2(acc[mt][nt][2] + bv.x, acc[mt][nt][3] + bv.y);
            *reinterpret_cast<float2*>(Cb + (long long)r0 * ldc + col)       = o0;
            *reinterpret_cast<float2*>(Cb + (long long)(r0 + 8) * ldc + col) = o1;
        }
    }
}

// ================= bf16 2-plane mma.sync GEMM (output projection) ==========
__global__ __launch_bounds__(256, 1)
void mma_gemm_bf16(const float* __restrict__ A, int lda,
                   const float* __restrict__ Bg, int ldb,
                   float* __restrict__ Cm, int ldc,
                   int K, const float* __restrict__ bias) {
    constexpr int BN   = 128;
    constexpr int SA   = 36;
    constexpr int SB   = BN + 4;
    constexpr int A_EL = 128 * SA;
    constexpr int B_EL = 32 * SB;

    extern __shared__ float sm[];
    float* smA = sm;
    float* smB = sm + 2 * A_EL;
    uint32_t smA_u = smem_u32(smA);
    uint32_t smB_u = smem_u32(smB);

    const int tid  = threadIdx.x;
    const int lane = tid & 31;
    const int wid  = tid >> 5;
    const int wm   = wid & 1;
    const int wn   = wid >> 1;
    const int gid  = lane >> 2;
    const int tig  = lane & 3;

    const int n0 = blockIdx.x * BN;
    const float* Ab = A + (long long)blockIdx.y * 128 * lda;
    const int NC = K >> 5;

    float acc[4][4][4];
    #pragma unroll
    for (int mt = 0; mt < 4; mt++)
        #pragma unroll
        for (int nt = 0; nt < 4; nt++)
            #pragma unroll
            for (int i = 0; i < 4; i++) acc[mt][nt][i] = 0.f;

    auto load_chunk = [&](int c, int st) {
        #pragma unroll
        for (int j = 0; j < 4; j++) {
            int idx = tid + j * 256;
            int r = idx >> 3, s = idx & 7;
            cp_async16(smA_u + (uint32_t)((st * A_EL + r * SA + s * 4) << 2),
                       Ab + (long long)r * lda + c * 32 + s * 4);
        }
        #pragma unroll
        for (int j = 0; j < 4; j++) {
            int idx = tid + j * 256;
            int r = idx >> 5, s = idx & 31;
            cp_async16(smB_u + (uint32_t)((st * B_EL + r * SB + s * 4) << 2),
                       Bg + (long long)(c * 32 + r) * ldb + n0 + s * 4);
        }
        asm volatile("cp.async.commit_group;" ::: "memory");
    };

    load_chunk(0, 0);
    for (int c = 0; c < NC; c++) {
        const int st = c & 1;
        if (c + 1 < NC) {
            load_chunk(c + 1, st ^ 1);
            asm volatile("cp.async.wait_group 1;" ::: "memory");
        } else {
            asm volatile("cp.async.wait_group 0;" ::: "memory");
        }
        __syncthreads();

        const float* cA = smA + st * A_EL;
        const float* cB = smB + st * B_EL;
        #pragma unroll
        for (int ks2 = 0; ks2 < 2; ks2++) {
            const int k0 = ks2 * 16;
            uint32_t ah[4][4], al[4][4];
            #pragma unroll
            for (int mt = 0; mt < 4; mt++) {
                const float* p = cA + (wm * 64 + mt * 16 + gid) * SA + k0 + 2 * tig;
                split2(p[0],          p[1],          ah[mt][0], al[mt][0]);
                split2(p[8 * SA],     p[8 * SA + 1], ah[mt][1], al[mt][1]);
                split2(p[8],          p[9],          ah[mt][2], al[mt][2]);
                split2(p[8 * SA + 8], p[8 * SA + 9], ah[mt][3], al[mt][3]);
            }
            uint32_t bh[4][2], bl[4][2];
            #pragma unroll
            for (int nt = 0; nt < 4; nt++) {
                const float* q = cB + (k0 + 2 * tig) * SB + wn * 32 + nt * 8 + gid;
                split2(q[0],      q[SB],     bh[nt][0], bl[nt][0]);
                split2(q[8 * SB], q[9 * SB], bh[nt][1], bl[nt][1]);
            }
            #pragma unroll
            for (int mt = 0; mt < 4; mt++)
                #pragma unroll
                for (int nt = 0; nt < 4; nt++) {
                    mma_bf16(acc[mt][nt], ah[mt], bl[nt]);
                    mma_bf16(acc[mt][nt], al[mt], bh[nt]);
                    mma_bf16(acc[mt][nt], ah[mt], bh[nt]);
                }
        }
        __syncthreads();
    }

    #pragma unroll
    for (int mt = 0; mt < 4; mt++) {
        int r0 = blockIdx.y * 128 + wm * 64 + mt * 16 + gid;
        #pragma unroll
        for (int nt = 0; nt < 4; nt++) {
            int col = n0 + wn * 32 + nt * 8 + tig * 2;
            float2 bv = bias ? *reinterpret_cast<const float2*>(bias + col)
                             : make_float2(0.f, 0.f);
            float2 o0 = make_float2(acc[mt][nt][0] + bv.x, acc[mt][nt][1] + bv.y);
            float2 o1 = make_float2(acc[mt][nt][2] + bv.x, acc[mt][nt][3] + bv.y);
            *reinterpret_cast<float2*>(Cm + (long long)r0 * ldc + col)       = o0;
            *reinterpret_cast<float2*>(Cm + (long long)(r0 + 8) * ldc + col) = o1;
        }
    }
}

// ---------------- spike gate ----------------------------------------------
__global__ void spike_kernel(const float* __restrict__ x,
                             const float* __restrict__ w_sur,
                             const float* __restrict__ b_sur,
                             const float* __restrict__ thr) {
    int row = blockIdx.x;
    const float4* xr = reinterpret_cast<const float4*>(x + (long long)row * Cn);
    const float4* wr = reinterpret_cast<const float4*>(w_sur);
    float s = 0.f;
    for (int i = threadIdx.x; i < Cn / 4; i += blockDim.x) {
        float4 a = xr[i], w = wr[i];
        s += a.x * w.x + a.y * w.y + a.z * w.z + a.w * w.w;
    }
    #pragma unroll
    for (int o = 16; o; o >>= 1) s += __shfl_xor_sync(0xffffffffu, s, o);
    __shared__ float smv[4];
    if ((threadIdx.x & 31) == 0) smv[threadIdx.x >> 5] = s;
    __syncthreads();
    if (threadIdx.x == 0) {
        float zz = smv[0] + smv[1] + smv[2] + smv[3] + b_sur[0];
        float imp = 1.f / (1.f + expf(-zz));
        g_spike[row] = (imp > thr[0]) ? 1.f : 0.f;
    }
}

// ---------------- compact spiking query indices per batch -----------------
__global__ void compact_kernel() {      // grid Bn, block 1024
    int b = blockIdx.x, t = threadIdx.x;
    __shared__ int pre[Tn];
    int s = (g_spike[b * Tn + t] > 0.f) ? 1 : 0;
    pre[t] = s;
    __syncthreads();
    for (int off = 1; off < Tn; off <<= 1) {
        int v = (t >= off) ? pre[t - off] : 0;
        __syncthreads();
        pre[t] += v;
        __syncthreads();
    }
    if (s) g_idx[b * Tn + pre[t] - 1] = t;
    if (t == Tn - 1) g_cnt[b] = pre[Tn - 1];
}

// ---------------- expmap0 split + V repack --------------------------------
__global__ void expmap_kernel() {
    int wid  = (blockIdx.x * blockDim.x + threadIdx.x) >> 5;
    int lane = threadIdx.x & 31;
    if (wid >= BH * Tn) return;
    int bh = wid >> 10;
    int t  = wid & (Tn - 1);
    int b  = bh >> 4;
    int h  = bh & (Hn - 1);
    long long base = (long long)(b * Tn + t) * NQKV + h * Dn;
    const float* q = g_qkv + base;
    const float* k = q + Cn;
    const float* v = q + 2 * Cn;
    long long o = (long long)wid * Dn;
    {
        float u0v = q[lane], u1v = q[lane + 32];
        float ss = u0v * u0v + u1v * u1v;
        #pragma unroll
        for (int off = 16; off; off >>= 1) ss += __shfl_xor_sync(0xffffffffu, ss, off);
        float u0 = __shfl_sync(0xffffffffu, u0v, 0);
        float mink = ss - 2.f * u0 * u0;
        float nom  = sqrtf(fmaxf(mink, 1e-8f));
        float tq   = coshf(nom);
        float fac  = sinhf(nom) / nom;
        g_Lq[o + lane]      = (lane == 0) ? tq : fac * u0v;
        g_Lq[o + lane + 32] = fac * u1v;
    }
    {
        float u0v = k[lane], u1v = k[lane + 32];
        float ss = u0v * u0v + u1v * u1v;
        #pragma unroll
        for (int off = 16; off; off >>= 1) ss += __shfl_xor_sync(0xffffffffu, ss, off);
        float u0 = __shfl_sync(0xffffffffu, u0v, 0);
        float mink = ss - 2.f * u0 * u0;
        float nom  = sqrtf(fmaxf(mink, 1e-8f));
        float tk   = coshf(nom);
        float fac  = sinhf(nom) / nom;
        g_Lk[o + lane]      = (lane == 0) ? tk : -fac * u0v;
        g_Lk[o + lane + 32] = -fac * u1v;
    }
    g_V[o + lane]      = v[lane];
    g_V[o + lane + 32] = v[lane + 32];
}

// ================= fused flash attention (compacted spiking queries) =======
// grid (8, BH), 256 threads / 8 warps; each warp owns 16 query rows.
// S-tile: tf32 3x.  P kept in registers (bf16 2-plane) -> PV: m16n8k16 bf16.
__global__ __launch_bounds__(256, 1)
void flash_kernel() {
    const int bh = blockIdx.y;
    const int b  = bh >> 4;
    const int h  = bh & (Hn - 1);
    const int qt = blockIdx.x;
    const int nb = g_cnt[b];
    if (qt * 128 >= nb) return;

    extern __shared__ float fs[];
    float* sQ = fs;                        // 128 x 68
    float* sK = sQ + 128 * 68;             // 2 x 64 x 68
    float* sV = sK + 2 * 64 * 68;          // 2 x 64 x 68
    int*   sT = (int*)(sV + 2 * 64 * 68);  // 128
    uint32_t uQ = smem_u32(sQ), uK = smem_u32(sK), uV = smem_u32(sV);

    const int tid  = threadIdx.x;
    const int lane = tid & 31;
    const int w    = tid >> 5;
    const int gid  = lane >> 2;
    const int tig  = lane & 3;

    if (tid < 128) {
        int ip = qt * 128 + tid;
        sT[tid] = (ip < nb) ? g_idx[b * Tn + ip] : -1;
    }
    __syncthreads();

    const int ilast = min(nb - 1, qt * 128 + 127);
    const int jmax  = g_idx[b * Tn + ilast];
    const int nj    = (jmax >> 6) + 1;

    const float* Lqb = g_Lq + (long long)bh * Tn * Dn;
    const float* Lkb = g_Lk + (long long)bh * Tn * Dn;
    const float* Vb  = g_V  + (long long)bh * Tn * Dn;

    #pragma unroll
    for (int i = 0; i < 8; i++) {
        int f4 = tid + i * 256;
        int r = f4 >> 4, s = f4 & 15;
        int t = sT[r]; if (t < 0) t = 0;
        cp_async16(uQ + (uint32_t)((r * 68 + s * 4) << 2), Lqb + (long long)t * 64 + s * 4);
    }
    auto loadKV = [&](int jt, int st) {
        #pragma unroll
        for (int i = 0; i < 4; i++) {
            int f4 = tid + i * 256;
            int r = f4 >> 4, s = f4 & 15;
            long long src = (long long)(jt * 64 + r) * 64 + s * 4;
            uint32_t off = (uint32_t)((st * 64 * 68 + r * 68 + s * 4) << 2);
            cp_async16(uK + off, Lkb + src);
            cp_async16(uV + off, Vb + src);
        }
        asm volatile("cp.async.commit_group;" ::: "memory");
    };
    loadKV(0, 0);

    const int t0 = sT[w * 16 + gid];
    const int t1 = sT[w * 16 + gid + 8];

    float m0 = -INFINITY, m1 = -INFINITY, l0 = 0.f, l1 = 0.f;
    float yacc[8][4];
    #pragma unroll
    for (int nt = 0; nt < 8; nt++)
        #pragma unroll
        for (int i = 0; i < 4; i++) yacc[nt][i] = 0.f;

    for (int jt = 0; jt < nj; jt++) {
        const int st = jt & 1;
        const int j0 = jt * 64;
        if (jt > 0) __syncthreads();
        if (jt + 1 < nj) {
            loadKV(jt + 1, st ^ 1);
            asm volatile("cp.async.wait_group 1;" ::: "memory");
        } else {
            asm volatile("cp.async.wait_group 0;" ::: "memory");
        }
        __syncthreads();

        const float* cK = sK + st * 64 * 68;
        const float* cV = sV + st * 64 * 68;

        // ---- S tile = Lq . Lk^T  (tf32 3x) ----
        float sacc[8][4];
        #pragma unroll
        for (int nt = 0; nt < 8; nt++)
            #pragma unroll
            for (int i = 0; i < 4; i++) sacc[nt][i] = 0.f;

        #pragma unroll
        for (int ks = 0; ks < 8; ks++) {
            const int k0 = ks * 8;
            const float* pA = sQ + (w * 16 + gid) * 68 + k0 + tig;
            float a0 = pA[0], a1 = pA[8 * 68], a2 = pA[4], a3 = pA[8 * 68 + 4];
            uint32_t ah[4], al[4];
            ah[0] = cvt_tf32(a0); al[0] = cvt_tf32(a0 - __uint_as_float(ah[0]));
            ah[1] = cvt_tf32(a1); al[1] = cvt_tf32(a1 - __uint_as_float(ah[1]));
            ah[2] = cvt_tf32(a2); al[2] = cvt_tf32(a2 - __uint_as_float(ah[2]));
            ah[3] = cvt_tf32(a3); al[3] = cvt_tf32(a3 - __uint_as_float(ah[3]));
            #pragma unroll
            for (int nt = 0; nt < 8; nt++) {
                const float* pB = cK + (nt * 8 + gid) * 68 + k0 + tig;
                float b0 = pB[0], b1 = pB[4];
                uint32_t bh2[2], bl2[2];
                bh2[0] = cvt_tf32(b0); bl2[0] = cvt_tf32(b0 - __uint_as_float(bh2[0]));
                bh2[1] = cvt_tf32(b1); bl2[1] = cvt_tf32(b1 - __uint_as_float(bh2[1]));
                mma_tf32(sacc[nt], al, bh2);
                mma_tf32(sacc[nt], ah, bl2);
                mma_tf32(sacc[nt], ah, bh2);
            }
        }

        // ---- epilogue: acosh score + online softmax (fast math) ----
        float mx0 = -INFINITY, mx1 = -INFINITY;
        #pragma unroll
        for (int nt = 0; nt < 8; nt++) {
            #pragma unroll
            for (int e = 0; e < 4; e++) {
                int j  = j0 + nt * 8 + 2 * tig + (e & 1);
                int tr = (e < 2) ? t0 : t1;
                float s;
                if (j > tr) s = -INFINITY;
                else {
                    float v = fmaxf(sacc[nt][e], 1.0f + 1e-7f);
                    float dd = __logf(v + sqrtf(v * v - 1.f));
                    s = -dd * dd * 0.125f;
                }
                sacc[nt][e] = s;
                if (e < 2) mx0 = fmaxf(mx0, s); else mx1 = fmaxf(mx1, s);
            }
        }
        mx0 = fmaxf(mx0, __shfl_xor_sync(0xffffffffu, mx0, 1));
        mx0 = fmaxf(mx0, __shfl_xor_sync(0xffffffffu, mx0, 2));
        mx1 = fmaxf(mx1, __shfl_xor_sync(0xffffffffu, mx1, 1));
        mx1 = fmaxf(mx1, __shfl_xor_sync(0xffffffffu, mx1, 2));
        float mn0 = fmaxf(m0, mx0), mn1 = fmaxf(m1, mx1);
        float al0 = (mn0 == -INFINITY) ? 0.f : __expf(m0 - mn0);
        float al1 = (mn1 == -INFINITY) ? 0.f : __expf(m1 - mn1);
        m0 = mn0; m1 = mn1;

        float ps0 = 0.f, ps1 = 0.f;
        #pragma unroll
        for (int nt = 0; nt < 8; nt++) {
            float p0 = (mn0 == -INFINITY) ? 0.f : __expf(sacc[nt][0] - mn0);
            float p1 = (mn0 == -INFINITY) ? 0.f : __expf(sacc[nt][1] - mn0);
            float p2 = (mn1 == -INFINITY) ? 0.f : __expf(sacc[nt][2] - mn1);
            float p3 = (mn1 == -INFINITY) ? 0.f : __expf(sacc[nt][3] - mn1);
            sacc[nt][0] = p0; sacc[nt][1] = p1; sacc[nt][2] = p2; sacc[nt][3] = p3;
            ps0 += p0 + p1; ps1 += p2 + p3;
        }
        l0 = l0 * al0 + ps0;
        l1 = l1 * al1 + ps1;
        #pragma unroll
        for (int nt = 0; nt < 8; nt++) {
            yacc[nt][0] *= al0; yacc[nt][1] *= al0;
            yacc[nt][2] *= al1; yacc[nt][3] *= al1;
        }

        // ---- P fragments in registers (bf16 2-plane), no smem round-trip ----
        uint32_t ph[4][4], pl[4][4];
        #pragma unroll
        for (int kc = 0; kc < 4; kc++) {
            split2(sacc[2 * kc][0],     sacc[2 * kc][1],     ph[kc][0], pl[kc][0]);
            split2(sacc[2 * kc][2],     sacc[2 * kc][3],     ph[kc][1], pl[kc][1]);
            split2(sacc[2 * kc + 1][0], sacc[2 * kc + 1][1], ph[kc][2], pl[kc][2]);
            split2(sacc[2 * kc + 1][2], sacc[2 * kc + 1][3], ph[kc][3], pl[kc][3]);
        }

        // ---- y += P . V  (bf16 m16n8k16, 3 products) ----
        #pragma unroll
        for (int kc = 0; kc < 4; kc++) {
            #pragma unroll
            for (int nt = 0; nt < 8; nt++) {
                const float* pv = cV + (kc * 16 + 2 * tig) * 68 + nt * 8 + gid;
                uint32_t vh[2], vl[2];
                split2(pv[0],      pv[68],     vh[0], vl[0]);
                split2(pv[8 * 68], pv[9 * 68], vh[1], vl[1]);
                mma_bf16(yacc[nt], ph[kc], vl);
                mma_bf16(yacc[nt], pl[kc], vh);
                mma_bf16(yacc[nt], ph[kc], vh);
            }
        }
    }

    // ---- finalize: divide by l, scatter to g_y ----
    l0 += __shfl_xor_sync(0xffffffffu, l0, 1);
    l0 += __shfl_xor_sync(0xffffffffu, l0, 2);
    l1 += __shfl_xor_sync(0xffffffffu, l1, 1);
    l1 += __shfl_xor_sync(0xffffffffu, l1, 2);
    float inv0 = 1.f / l0, inv1 = 1.f / l1;
    #pragma unroll
    for (int nt = 0; nt < 8; nt++) {
        int col = h * 64 + nt * 8 + 2 * tig;
        if (t0 >= 0)
            *reinterpret_cast<float2*>(g_y + (long long)(b * Tn + t0) * Cn + col)
                = make_float2(yacc[nt][0] * inv0, yacc[nt][1] * inv0);
        if (t1 >= 0)
            *reinterpret_cast<float2*>(g_y + (long long)(b * Tn + t1) * Cn + col)
                = make_float2(yacc[nt][2] * inv1, yacc[nt][3] * inv1);
    }
}

// ---------------- launch ---------------------------------------------------
extern "C" void kernel_launch(void* const* d_in, const int* in_sizes, int n_in,
                              void* d_out, int out_size) {
    const float* x     = (const float*)d_in[0];
    const float* W_qkv = (const float*)d_in[1];
    const float* b_qkv = (const float*)d_in[2];
    const float* W_out = (const float*)d_in[3];
    const float* b_out = (const float*)d_in[4];
    const float* w_sur = (const float*)d_in[5];
    const float* b_sur = (const float*)d_in[6];
    const float* thr   = (const float*)d_in[7];
    float* out = (float*)d_out;

    float *p_qkv, *p_y;
    cudaGetSymbolAddress((void**)&p_qkv, g_qkv);
    cudaGetSymbolAddress((void**)&p_y,   g_y);

    const int smem128 = (2 * 128 * 36 + 2 * 32 * 132) * 4;                 // 70656
    const int smemFl  = (128 * 68 + 4 * 64 * 68) * 4 + 512;                // ~105KB
    cudaFuncSetAttribute(mma_gemm<128>, cudaFuncAttributeMaxDynamicSharedMemorySize, smem128);
    cudaFuncSetAttribute(mma_gemm_bf16, cudaFuncAttributeMaxDynamicSharedMemorySize, smem128);
    cudaFuncSetAttribute(flash_kernel,  cudaFuncAttributeMaxDynamicSharedMemorySize, smemFl);

    // 1) spike gate + compaction
    spike_kernel<<<BT, 128>>>(x, w_sur, b_sur, thr);
    compact_kernel<<<Bn, Tn>>>();

    // 2) QKV GEMM (tf32 3x — precision-critical path)
    mma_gemm<128><<<dim3(NQKV / 128, BT / 128, 1), 256, smem128>>>(
        x, Cn, W_qkv, NQKV, p_qkv, NQKV, Cn, b_qkv);

    // 3) expmap + V repack
    expmap_kernel<<<(BH * Tn) / 8, 256>>>();

    // 4) zero y (non-spiking rows stay zero)
    cudaMemsetAsync(p_y, 0, (size_t)BT * Cn * sizeof(float));

    // 5) fused attention over compacted spiking queries
    flash_kernel<<<dim3(Tn / 128, BH), 256, smemFl>>>();

    // 6) output GEMM (bf16 2-plane — direct path, half the MMAs)
    mma_gemm_bf16<<<dim3(Cn / 128, BT / 128, 1), 256, smem128>>>(
        p_y, Cn, W_out, Cn, out, Cn, Cn, b_out);
}

// round 8
// speedup vs baseline: 2.2109x; 1.2185x over previous
#include <cuda_runtime.h>
#include <cuda_bf16.h>
#include <math.h>
#include <stdint.h>

// Problem constants
#define Bn 4
#define Tn 1024
#define Cn 1024
#define Hn 16
#define Dn 64
constexpr int BT   = Bn * Tn;          // 4096
constexpr int BH   = Bn * Hn;          // 64
constexpr int NQKV = 3 * Cn;           // 3072

// ---------------- scratch (static device allocations) ---------------------
__device__ float    g_qkv[BT * NQKV];          // 48 MB
__device__ float    g_Lq [BH * Tn * Dn];       // 16 MB (fp32 Q lorentz)
__device__ float    g_Kph[BH * Tn * Dn];       // 16 MB K lorentz tf32-hi plane
__device__ float    g_Kpl[BH * Tn * Dn];       // 16 MB K residual plane
__device__ uint32_t g_Vph[BH * (Tn/2) * Dn];   // 8 MB V bf16x2 hi (t-pairs)
__device__ uint32_t g_Vpl[BH * (Tn/2) * Dn];   // 8 MB V bf16x2 lo
__device__ float    g_y  [BT * Cn];            // 16 MB
__device__ float    g_spike[BT];
__device__ int      g_idx[BT];                 // compacted spiking t per batch
__device__ int      g_cnt[Bn];

// ======================= helpers ==========================================
__device__ __forceinline__ uint32_t smem_u32(const void* p) {
    uint32_t a;
    asm("{ .reg .u64 t; cvta.to.shared.u64 t, %1; cvt.u32.u64 %0, t; }" : "=r"(a) : "l"(p));
    return a;
}
__device__ __forceinline__ uint32_t cvt_tf32(float x) {
    uint32_t r; asm("cvt.rna.tf32.f32 %0, %1;" : "=r"(r) : "f"(x)); return r;
}
__device__ __forceinline__ void mma_tf32(float* c, const uint32_t* a, const uint32_t* b) {
    asm volatile(
        "mma.sync.aligned.m16n8k8.row.col.f32.tf32.tf32.f32 "
        "{%0,%1,%2,%3}, {%4,%5,%6,%7}, {%8,%9}, {%0,%1,%2,%3};"
        : "+f"(c[0]), "+f"(c[1]), "+f"(c[2]), "+f"(c[3])
        : "r"(a[0]), "r"(a[1]), "r"(a[2]), "r"(a[3]), "r"(b[0]), "r"(b[1]));
}
__device__ __forceinline__ void mma_bf16(float* c, const uint32_t* a, const uint32_t* b) {
    asm volatile(
        "mma.sync.aligned.m16n8k16.row.col.f32.bf16.bf16.f32 "
        "{%0,%1,%2,%3}, {%4,%5,%6,%7}, {%8,%9}, {%0,%1,%2,%3};"
        : "+f"(c[0]), "+f"(c[1]), "+f"(c[2]), "+f"(c[3])
        : "r"(a[0]), "r"(a[1]), "r"(a[2]), "r"(a[3]), "r"(b[0]), "r"(b[1]));
}
__device__ __forceinline__ void split2(float x, float y, uint32_t& h, uint32_t& l) {
    __nv_bfloat162 t = __floats2bfloat162_rn(x, y);
    uint32_t u = *reinterpret_cast<uint32_t*>(&t);
    h = u;
    float lx = x - __uint_as_float(u << 16);
    float ly = y - __uint_as_float(u & 0xFFFF0000u);
    __nv_bfloat162 t2 = __floats2bfloat162_rn(lx, ly);
    l = *reinterpret_cast<uint32_t*>(&t2);
}
__device__ __forceinline__ void cp_async16(uint32_t dst, const void* src) {
    asm volatile("cp.async.cg.shared.global [%0], [%1], 16;" :: "r"(dst), "l"(src));
}

// ======================= tf32 3x dense GEMM (KV part) ======================
__global__ __launch_bounds__(256, 1)
void mma_gemm(const float* __restrict__ A, int lda,
              const float* __restrict__ Bg, int ldb,
              float* __restrict__ Cm, int ldc,
              int K, const float* __restrict__ bias) {
    constexpr int BN   = 128;
    constexpr int SA   = 36;
    constexpr int SB   = BN + 4;
    constexpr int A_EL = 128 * SA;
    constexpr int B_EL = 32 * SB;

    extern __shared__ float sm[];
    float* smA = sm;
    float* smB = sm + 2 * A_EL;
    uint32_t smA_u = smem_u32(smA);
    uint32_t smB_u = smem_u32(smB);

    const int tid  = threadIdx.x;
    const int lane = tid & 31;
    const int wid  = tid >> 5;
    const int wm   = wid & 1;
    const int wn   = wid >> 1;
    const int gid  = lane >> 2;
    const int tig  = lane & 3;

    const int n0 = blockIdx.x * BN;
    const float* Ab = A + (long long)blockIdx.y * 128 * lda;
    const int NC = K >> 5;

    float acc[4][4][4];
    #pragma unroll
    for (int mt = 0; mt < 4; mt++)
        #pragma unroll
        for (int nt = 0; nt < 4; nt++)
            #pragma unroll
            for (int i = 0; i < 4; i++) acc[mt][nt][i] = 0.f;

    auto load_chunk = [&](int c, int st) {
        #pragma unroll
        for (int j = 0; j < 4; j++) {
            int idx = tid + j * 256;
            int r = idx >> 3, s = idx & 7;
            cp_async16(smA_u + (uint32_t)((st * A_EL + r * SA + s * 4) << 2),
                       Ab + (long long)r * lda + c * 32 + s * 4);
        }
        #pragma unroll
        for (int j = 0; j < 4; j++) {
            int idx = tid + j * 256;
            int r = idx >> 5, s = idx & 31;
            cp_async16(smB_u + (uint32_t)((st * B_EL + r * SB + s * 4) << 2),
                       Bg + (long long)(c * 32 + r) * ldb + n0 + s * 4);
        }
        asm volatile("cp.async.commit_group;" ::: "memory");
    };

    load_chunk(0, 0);
    for (int c = 0; c < NC; c++) {
        const int st = c & 1;
        if (c + 1 < NC) {
            load_chunk(c + 1, st ^ 1);
            asm volatile("cp.async.wait_group 1;" ::: "memory");
        } else {
            asm volatile("cp.async.wait_group 0;" ::: "memory");
        }
        __syncthreads();

        const float* cA = smA + st * A_EL;
        const float* cB = smB + st * B_EL;
        #pragma unroll
        for (int ks = 0; ks < 4; ks++) {
            const int k0 = ks * 8;
            uint32_t ah[4][4], al[4][4];
            #pragma unroll
            for (int mt = 0; mt < 4; mt++) {
                const float* p = cA + (wm * 64 + mt * 16 + gid) * SA + k0 + tig;
                float a0 = p[0], a1 = p[8 * SA], a2 = p[4], a3 = p[8 * SA + 4];
                ah[mt][0] = cvt_tf32(a0); al[mt][0] = cvt_tf32(a0 - __uint_as_float(ah[mt][0]));
                ah[mt][1] = cvt_tf32(a1); al[mt][1] = cvt_tf32(a1 - __uint_as_float(ah[mt][1]));
                ah[mt][2] = cvt_tf32(a2); al[mt][2] = cvt_tf32(a2 - __uint_as_float(ah[mt][2]));
                ah[mt][3] = cvt_tf32(a3); al[mt][3] = cvt_tf32(a3 - __uint_as_float(ah[mt][3]));
            }
            uint32_t bh[4][2], bl[4][2];
            #pragma unroll
            for (int nt = 0; nt < 4; nt++) {
                const float* p = cB + (k0 + tig) * SB + wn * 32 + nt * 8 + gid;
                float b0 = p[0], b1 = p[4 * SB];
                bh[nt][0] = cvt_tf32(b0); bl[nt][0] = cvt_tf32(b0 - __uint_as_float(bh[nt][0]));
                bh[nt][1] = cvt_tf32(b1); bl[nt][1] = cvt_tf32(b1 - __uint_as_float(bh[nt][1]));
            }
            #pragma unroll
            for (int mt = 0; mt < 4; mt++)
                #pragma unroll
                for (int nt = 0; nt < 4; nt++) {
                    mma_tf32(acc[mt][nt], al[mt], bh[nt]);
                    mma_tf32(acc[mt][nt], ah[mt], bl[nt]);
                    mma_tf32(acc[mt][nt], ah[mt], bh[nt]);
                }
        }
        __syncthreads();
    }

    #pragma unroll
    for (int mt = 0; mt < 4; mt++) {
        int r0 = blockIdx.y * 128 + wm * 64 + mt * 16 + gid;
        #pragma unroll
        for (int nt = 0; nt < 4; nt++) {
            int col = n0 + wn * 32 + nt * 8 + tig * 2;
            float2 bv = bias ? *reinterpret_cast<const float2*>(bias + col)
                             : make_float2(0.f, 0.f);
            float2 o0 = make_float2(acc[mt][nt][0] + bv.x, acc[mt][nt][1] + bv.y);
            float2 o1 = make_float2(acc[mt][nt][2] + bv.x, acc[mt][nt][3] + bv.y);
            *reinterpret_cast<float2*>(Cm + (long long)r0 * ldc + col)       = o0;
            *reinterpret_cast<float2*>(Cm + (long long)(r0 + 8) * ldc + col) = o1;
        }
    }
}

// ============== tf32 3x gathered GEMM (Q part, spiking rows) ===============
__global__ __launch_bounds__(256, 1)
void mma_gemm_q(const float* __restrict__ x,
                const float* __restrict__ Wq,
                float* __restrict__ qkv,
                const float* __restrict__ bias) {
    constexpr int SA   = 36;
    constexpr int SB   = 132;
    constexpr int A_EL = 128 * SA;
    constexpr int B_EL = 32 * SB;

    __shared__ int sRow[128];
    extern __shared__ float sm[];
    float* smA = sm;
    float* smB = sm + 2 * A_EL;
    uint32_t smA_u = smem_u32(smA);
    uint32_t smB_u = smem_u32(smB);

    const int b    = blockIdx.y >> 3;
    const int base = (blockIdx.y & 7) * 128;
    const int cnt  = g_cnt[b];
    if (base >= cnt) return;

    const int tid  = threadIdx.x;
    const int lane = tid & 31;
    const int wid  = tid >> 5;
    const int wm   = wid & 1;
    const int wn   = wid >> 1;
    const int gid  = lane >> 2;
    const int tig  = lane & 3;

    if (tid < 128) {
        int ip = base + tid;
        sRow[tid] = (ip < cnt) ? g_idx[b * Tn + ip] : -1;
    }
    __syncthreads();
    const int safe = sRow[0];

    const int n0 = blockIdx.x * 128;
    const float* Ab = x + (long long)b * Tn * Cn;

    float acc[4][4][4];
    #pragma unroll
    for (int mt = 0; mt < 4; mt++)
        #pragma unroll
        for (int nt = 0; nt < 4; nt++)
            #pragma unroll
            for (int i = 0; i < 4; i++) acc[mt][nt][i] = 0.f;

    auto load_chunk = [&](int c, int st) {
        #pragma unroll
        for (int j = 0; j < 4; j++) {
            int idx = tid + j * 256;
            int r = idx >> 3, s = idx & 7;
            int tr = sRow[r]; if (tr < 0) tr = safe;
            cp_async16(smA_u + (uint32_t)((st * A_EL + r * SA + s * 4) << 2),
                       Ab + (long long)tr * Cn + c * 32 + s * 4);
        }
        #pragma unroll
        for (int j = 0; j < 4; j++) {
            int idx = tid + j * 256;
            int r = idx >> 5, s = idx & 31;
            cp_async16(smB_u + (uint32_t)((st * B_EL + r * SB + s * 4) << 2),
                       Wq + (long long)(c * 32 + r) * NQKV + n0 + s * 4);
        }
        asm volatile("cp.async.commit_group;" ::: "memory");
    };

    load_chunk(0, 0);
    for (int c = 0; c < 32; c++) {
        const int st = c & 1;
        if (c + 1 < 32) {
            load_chunk(c + 1, st ^ 1);
            asm volatile("cp.async.wait_group 1;" ::: "memory");
        } else {
            asm volatile("cp.async.wait_group 0;" ::: "memory");
        }
        __syncthreads();

        const float* cA = smA + st * A_EL;
        const float* cB = smB + st * B_EL;
        #pragma unroll
        for (int ks = 0; ks < 4; ks++) {
            const int k0 = ks * 8;
            uint32_t ah[4][4], al[4][4];
            #pragma unroll
            for (int mt = 0; mt < 4; mt++) {
                const float* p = cA + (wm * 64 + mt * 16 + gid) * SA + k0 + tig;
                float a0 = p[0], a1 = p[8 * SA], a2 = p[4], a3 = p[8 * SA + 4];
                ah[mt][0] = cvt_tf32(a0); al[mt][0] = cvt_tf32(a0 - __uint_as_float(ah[mt][0]));
                ah[mt][1] = cvt_tf32(a1); al[mt][1] = cvt_tf32(a1 - __uint_as_float(ah[mt][1]));
                ah[mt][2] = cvt_tf32(a2); al[mt][2] = cvt_tf32(a2 - __uint_as_float(ah[mt][2]));
                ah[mt][3] = cvt_tf32(a3); al[mt][3] = cvt_tf32(a3 - __uint_as_float(ah[mt][3]));
            }
            uint32_t bh[4][2], bl[4][2];
            #pragma unroll
            for (int nt = 0; nt < 4; nt++) {
                const float* p = cB + (k0 + tig) * SB + wn * 32 + nt * 8 + gid;
                float b0 = p[0], b1 = p[4 * SB];
                bh[nt][0] = cvt_tf32(b0); bl[nt][0] = cvt_tf32(b0 - __uint_as_float(bh[nt][0]));
                bh[nt][1] = cvt_tf32(b1); bl[nt][1] = cvt_tf32(b1 - __uint_as_float(bh[nt][1]));
            }
            #pragma unroll
            for (int mt = 0; mt < 4; mt++)
                #pragma unroll
                for (int nt = 0; nt < 4; nt++) {
                    mma_tf32(acc[mt][nt], al[mt], bh[nt]);
                    mma_tf32(acc[mt][nt], ah[mt], bl[nt]);
                    mma_tf32(acc[mt][nt], ah[mt], bh[nt]);
                }
        }
        __syncthreads();
    }

    #pragma unroll
    for (int mt = 0; mt < 4; mt++) {
        int rl = wm * 64 + mt * 16 + gid;
        int t0 = sRow[rl], t1 = sRow[rl + 8];
        #pragma unroll
        for (int nt = 0; nt < 4; nt++) {
            int col = n0 + wn * 32 + nt * 8 + tig * 2;
            float2 bv = *reinterpret_cast<const float2*>(bias + col);
            if (t0 >= 0)
                *reinterpret_cast<float2*>(qkv + ((long long)(b * Tn + t0)) * NQKV + col)
                    = make_float2(acc[mt][nt][0] + bv.x, acc[mt][nt][1] + bv.y);
            if (t1 >= 0)
                *reinterpret_cast<float2*>(qkv + ((long long)(b * Tn + t1)) * NQKV + col)
                    = make_float2(acc[mt][nt][2] + bv.x, acc[mt][nt][3] + bv.y);
        }
    }
}

// ============ bf16 2-plane gathered GEMM (out-proj, spiking rows) ==========
__global__ __launch_bounds__(256, 1)
void mma_gemm_o(const float* __restrict__ Wo,
                float* __restrict__ out,
                const float* __restrict__ bias) {
    constexpr int SA   = 36;
    constexpr int SB   = 132;
    constexpr int A_EL = 128 * SA;
    constexpr int B_EL = 32 * SB;

    __shared__ int sRow[128];
    extern __shared__ float sm[];
    float* smA = sm;
    float* smB = sm + 2 * A_EL;
    uint32_t smA_u = smem_u32(smA);
    uint32_t smB_u = smem_u32(smB);

    const int b    = blockIdx.y >> 3;
    const int base = (blockIdx.y & 7) * 128;
    const int cnt  = g_cnt[b];
    if (base >= cnt) return;

    const int tid  = threadIdx.x;
    const int lane = tid & 31;
    const int wid  = tid >> 5;
    const int wm   = wid & 1;
    const int wn   = wid >> 1;
    const int gid  = lane >> 2;
    const int tig  = lane & 3;

    if (tid < 128) {
        int ip = base + tid;
        sRow[tid] = (ip < cnt) ? g_idx[b * Tn + ip] : -1;
    }
    __syncthreads();
    const int safe = sRow[0];

    const int n0 = blockIdx.x * 128;
    const float* Ab = g_y + (long long)b * Tn * Cn;

    float acc[4][4][4];
    #pragma unroll
    for (int mt = 0; mt < 4; mt++)
        #pragma unroll
        for (int nt = 0; nt < 4; nt++)
            #pragma unroll
            for (int i = 0; i < 4; i++) acc[mt][nt][i] = 0.f;

    auto load_chunk = [&](int c, int st) {
        #pragma unroll
        for (int j = 0; j < 4; j++) {
            int idx = tid + j * 256;
            int r = idx >> 3, s = idx & 7;
            int tr = sRow[r]; if (tr < 0) tr = safe;
            cp_async16(smA_u + (uint32_t)((st * A_EL + r * SA + s * 4) << 2),
                       Ab + (long long)tr * Cn + c * 32 + s * 4);
        }
        #pragma unroll
        for (int j = 0; j < 4; j++) {
            int idx = tid + j * 256;
            int r = idx >> 5, s = idx & 31;
            cp_async16(smB_u + (uint32_t)((st * B_EL + r * SB + s * 4) << 2),
                       Wo + (long long)(c * 32 + r) * Cn + n0 + s * 4);
        }
        asm volatile("cp.async.commit_group;" ::: "memory");
    };

    load_chunk(0, 0);
    for (int c = 0; c < 32; c++) {
        const int st = c & 1;
        if (c + 1 < 32) {
            load_chunk(c + 1, st ^ 1);
            asm volatile("cp.async.wait_group 1;" ::: "memory");
        } else {
            asm volatile("cp.async.wait_group 0;" ::: "memory");
        }
        __syncthreads();

        const float* cA = smA + st * A_EL;
        const float* cB = smB + st * B_EL;
        #pragma unroll
        for (int ks2 = 0; ks2 < 2; ks2++) {
            const int k0 = ks2 * 16;
            uint32_t ah[4][4], al[4][4];
            #pragma unroll
            for (int mt = 0; mt < 4; mt++) {
                const float* p = cA + (wm * 64 + mt * 16 + gid) * SA + k0 + 2 * tig;
                split2(p[0],          p[1],          ah[mt][0], al[mt][0]);
                split2(p[8 * SA],     p[8 * SA + 1], ah[mt][1], al[mt][1]);
                split2(p[8],          p[9],          ah[mt][2], al[mt][2]);
                split2(p[8 * SA + 8], p[8 * SA + 9], ah[mt][3], al[mt][3]);
            }
            uint32_t bh[4][2], bl[4][2];
            #pragma unroll
            for (int nt = 0; nt < 4; nt++) {
                const float* q = cB + (k0 + 2 * tig) * SB + wn * 32 + nt * 8 + gid;
                split2(q[0],      q[SB],     bh[nt][0], bl[nt][0]);
                split2(q[8 * SB], q[9 * SB], bh[nt][1], bl[nt][1]);
            }
            #pragma unroll
            for (int mt = 0; mt < 4; mt++)
                #pragma unroll
                for (int nt = 0; nt < 4; nt++) {
                    mma_bf16(acc[mt][nt], ah[mt], bl[nt]);
                    mma_bf16(acc[mt][nt], al[mt], bh[nt]);
                    mma_bf16(acc[mt][nt], ah[mt], bh[nt]);
                }
        }
        __syncthreads();
    }

    #pragma unroll
    for (int mt = 0; mt < 4; mt++) {
        int rl = wm * 64 + mt * 16 + gid;
        int t0 = sRow[rl], t1 = sRow[rl + 8];
        #pragma unroll
        for (int nt = 0; nt < 4; nt++) {
            int col = n0 + wn * 32 + nt * 8 + tig * 2;
            float2 bv = *reinterpret_cast<const float2*>(bias + col);
            if (t0 >= 0)
                *reinterpret_cast<float2*>(out + (long long)(b * Tn + t0) * Cn + col)
                    = make_float2(acc[mt][nt][0] + bv.x, acc[mt][nt][1] + bv.y);
            if (t1 >= 0)
                *reinterpret_cast<float2*>(out + (long long)(b * Tn + t1) * Cn + col)
                    = make_float2(acc[mt][nt][2] + bv.x, acc[mt][nt][3] + bv.y);
        }
    }
}

// ---------------- spike gate ----------------------------------------------
__global__ void spike_kernel(const float* __restrict__ x,
                             const float* __restrict__ w_sur,
                             const float* __restrict__ b_sur,
                             const float* __restrict__ thr) {
    int row = blockIdx.x;
    const float4* xr = reinterpret_cast<const float4*>(x + (long long)row * Cn);
    const float4* wr = reinterpret_cast<const float4*>(w_sur);
    float s = 0.f;
    for (int i = threadIdx.x; i < Cn / 4; i += blockDim.x) {
        float4 a = xr[i], w = wr[i];
        s += a.x * w.x + a.y * w.y + a.z * w.z + a.w * w.w;
    }
    #pragma unroll
    for (int o = 16; o; o >>= 1) s += __shfl_xor_sync(0xffffffffu, s, o);
    __shared__ float smv[4];
    if ((threadIdx.x & 31) == 0) smv[threadIdx.x >> 5] = s;
    __syncthreads();
    if (threadIdx.x == 0) {
        float zz = smv[0] + smv[1] + smv[2] + smv[3] + b_sur[0];
        float imp = 1.f / (1.f + expf(-zz));
        g_spike[row] = (imp > thr[0]) ? 1.f : 0.f;
    }
}

// ---------------- compact spiking query indices per batch -----------------
__global__ void compact_kernel() {
    int b = blockIdx.x, t = threadIdx.x;
    __shared__ int pre[Tn];
    int s = (g_spike[b * Tn + t] > 0.f) ? 1 : 0;
    pre[t] = s;
    __syncthreads();
    for (int off = 1; off < Tn; off <<= 1) {
        int v = (t >= off) ? pre[t - off] : 0;
        __syncthreads();
        pre[t] += v;
        __syncthreads();
    }
    if (s) g_idx[b * Tn + pre[t] - 1] = t;
    if (t == Tn - 1) g_cnt[b] = pre[Tn - 1];
}

// ---------------- expmap0 split + operand pre-split (t-pairs) --------------
// one warp per (bh, t-pair): Lq fp32; Lk -> tf32 hi/lo planes; V -> bf16x2 pair planes
__global__ void expmap_kernel() {
    int wp   = (blockIdx.x * blockDim.x + threadIdx.x) >> 5;
    int lane = threadIdx.x & 31;
    if (wp >= BH * Tn / 2) return;
    int bh = wp >> 9;
    int t2 = wp & 511;
    int b  = bh >> 4;
    int h  = bh & (Hn - 1);
    int t0 = t2 * 2;

    const float* q0 = g_qkv + (long long)(b * Tn + t0) * NQKV + h * Dn;
    const float* q1 = q0 + NQKV;

    auto emap = [&](const float* u, float& o_lo, float& o_hi, bool neg) {
        float u0v = u[lane], u1v = u[lane + 32];
        float ss = u0v * u0v + u1v * u1v;
        #pragma unroll
        for (int off = 16; off; off >>= 1) ss += __shfl_xor_sync(0xffffffffu, ss, off);
        float u0 = __shfl_sync(0xffffffffu, u0v, 0);
        float mink = ss - 2.f * u0 * u0;
        float nom  = sqrtf(fmaxf(mink, 1e-8f));
        float tch  = coshf(nom);
        float fac  = sinhf(nom) / nom;
        o_lo = (lane == 0) ? tch : fac * u0v;
        o_hi = fac * u1v;
        if (neg) { if (lane) o_lo = -o_lo; o_hi = -o_hi; }
    };

    long long o0 = (long long)(bh * Tn + t0) * Dn;
    long long o1 = o0 + Dn;

    float lo, hi;
    emap(q0, lo, hi, false);
    g_Lq[o0 + lane] = lo; g_Lq[o0 + lane + 32] = hi;
    emap(q1, lo, hi, false);
    g_Lq[o1 + lane] = lo; g_Lq[o1 + lane + 32] = hi;

    auto pack_k = [&](float x, long long off) {
        uint32_t hb = cvt_tf32(x);
        float res = x - __uint_as_float(hb);
        g_Kph[off] = __uint_as_float(hb);
        g_Kpl[off] = __uint_as_float(cvt_tf32(res));
    };
    emap(q0 + Cn, lo, hi, true);
    pack_k(lo, o0 + lane); pack_k(hi, o0 + lane + 32);
    emap(q1 + Cn, lo, hi, true);
    pack_k(lo, o1 + lane); pack_k(hi, o1 + lane + 32);

    const float* v0 = q0 + 2 * Cn;
    const float* v1 = q1 + 2 * Cn;
    long long vo = (long long)(bh * 512 + t2) * 64;
    uint32_t ph, pl;
    split2(v0[lane], v1[lane], ph, pl);
    g_Vph[vo + lane] = ph; g_Vpl[vo + lane] = pl;
    split2(v0[lane + 32], v1[lane + 32], ph, pl);
    g_Vph[vo + lane + 32] = ph; g_Vpl[vo + lane + 32] = pl;
}

// ================= fused flash attention (compacted spiking queries) =======
// smem bytes: sQ 34816 | sK 2x(hi 17408 + lo 17408) | sV 2x(hi 9216 + lo 9216) | sT 512
__global__ __launch_bounds__(256, 1)
void flash_kernel() {
    const int bh = blockIdx.y;
    const int b  = bh >> 4;
    const int h  = bh & (Hn - 1);
    const int qt = gridDim.x - 1 - blockIdx.x;      // heavy tiles first
    const int nb = g_cnt[b];
    if (qt * 128 >= nb) return;

    extern __shared__ char fsb[];
    float* sQ = (float*)fsb;                            // 128 x 68 fp32
    char*  sKbase = fsb + 34816;                        // 2 stages x 34816
    char*  sVbase = fsb + 34816 + 69632;                // 2 stages x 18432
    int*   sT = (int*)(fsb + 34816 + 69632 + 36864);    // 128
    uint32_t uQ = smem_u32(sQ), uK = smem_u32(sKbase), uV = smem_u32(sVbase);

    const int tid  = threadIdx.x;
    const int lane = tid & 31;
    const int w    = tid >> 5;
    const int gid  = lane >> 2;
    const int tig  = lane & 3;

    if (tid < 128) {
        int ip = qt * 128 + tid;
        sT[tid] = (ip < nb) ? g_idx[b * Tn + ip] : -1;
    }
    __syncthreads();

    const int ilast = min(nb - 1, qt * 128 + 127);
    const int jmax  = g_idx[b * Tn + ilast];
    const int nj    = (jmax >> 6) + 1;

    const float*    Lqb = g_Lq  + (long long)bh * Tn * Dn;
    const float*    Khb = g_Kph + (long long)bh * Tn * Dn;
    const float*    Klb = g_Kpl + (long long)bh * Tn * Dn;
    const uint32_t* Vhb = g_Vph + (long long)bh * 512 * 64;
    const uint32_t* Vlb = g_Vpl + (long long)bh * 512 * 64;

    #pragma unroll
    for (int i = 0; i < 8; i++) {
        int f4 = tid + i * 256;
        int r = f4 >> 4, s = f4 & 15;
        int t = sT[r]; if (t < 0) t = 0;
        cp_async16(uQ + (uint32_t)((r * 68 + s * 4) << 2), Lqb + (long long)t * 64 + s * 4);
    }
    auto loadKV = [&](int jt, int st) {
        // K: 2 planes x 64 rows x 256B (stride 68 floats)
        #pragma unroll
        for (int i = 0; i < 8; i++) {
            int idx = tid + i * 256;
            int pl = idx >> 10, rem = idx & 1023;
            int r = rem >> 4, s = rem & 15;
            const float* src = (pl ? Klb : Khb) + (long long)(jt * 64 + r) * 64 + s * 4;
            cp_async16(uK + (uint32_t)(st * 34816 + pl * 17408 + r * 272 + s * 16), src);
        }
        // V: 2 planes x 32 pair-rows x 256B (stride 72 u32)
        #pragma unroll
        for (int i = 0; i < 4; i++) {
            int idx = tid + i * 256;
            int pl = idx >> 9, rem = idx & 511;
            int r = rem >> 4, s = rem & 15;
            const uint32_t* src = (pl ? Vlb : Vhb) + (long long)(jt * 32 + r) * 64 + s * 4;
            cp_async16(uV + (uint32_t)(st * 18432 + pl * 9216 + r * 288 + s * 16), src);
        }
        asm volatile("cp.async.commit_group;" ::: "memory");
    };
    loadKV(0, 0);

    const int t0 = sT[w * 16 + gid];
    const int t1 = sT[w * 16 + gid + 8];

    float m0 = -INFINITY, m1 = -INFINITY, l0 = 0.f, l1 = 0.f;
    float yacc[8][4];
    #pragma unroll
    for (int nt = 0; nt < 8; nt++)
        #pragma unroll
        for (int i = 0; i < 4; i++) yacc[nt][i] = 0.f;

    for (int jt = 0; jt < nj; jt++) {
        const int st = jt & 1;
        const int j0 = jt * 64;
        if (jt > 0) __syncthreads();
        if (jt + 1 < nj) {
            loadKV(jt + 1, st ^ 1);
            asm volatile("cp.async.wait_group 1;" ::: "memory");
        } else {
            asm volatile("cp.async.wait_group 0;" ::: "memory");
        }
        __syncthreads();

        const float* cKh = (const float*)(sKbase + st * 34816);
        const float* cKl = cKh + 4352;                     // +17408B
        const uint32_t* cVh = (const uint32_t*)(sVbase + st * 18432);
        const uint32_t* cVl = cVh + 2304;                  // +9216B

        // ---- S tile = Lq . Lk^T  (tf32 3x, K pre-split) ----
        float sacc[8][4];
        #pragma unroll
        for (int nt = 0; nt < 8; nt++)
            #pragma unroll
            for (int i = 0; i < 4; i++) sacc[nt][i] = 0.f;

        #pragma unroll
        for (int ks = 0; ks < 8; ks++) {
            const int k0 = ks * 8;
            const float* pA = sQ + (w * 16 + gid) * 68 + k0 + tig;
            float a0 = pA[0], a1 = pA[8 * 68], a2 = pA[4], a3 = pA[8 * 68 + 4];
            uint32_t ah[4], al[4];
            ah[0] = cvt_tf32(a0); al[0] = cvt_tf32(a0 - __uint_as_float(ah[0]));
            ah[1] = cvt_tf32(a1); al[1] = cvt_tf32(a1 - __uint_as_float(ah[1]));
            ah[2] = cvt_tf32(a2); al[2] = cvt_tf32(a2 - __uint_as_float(ah[2]));
            ah[3] = cvt_tf32(a3); al[3] = cvt_tf32(a3 - __uint_as_float(ah[3]));
            #pragma unroll
            for (int nt = 0; nt < 8; nt++) {
                const float* pBh = cKh + (nt * 8 + gid) * 68 + k0 + tig;
                const float* pBl = cKl + (nt * 8 + gid) * 68 + k0 + tig;
                uint32_t bh2[2], bl2[2];
                bh2[0] = __float_as_uint(pBh[0]); bh2[1] = __float_as_uint(pBh[4]);
                bl2[0] = __float_as_uint(pBl[0]); bl2[1] = __float_as_uint(pBl[4]);
                mma_tf32(sacc[nt], al, bh2);
                mma_tf32(sacc[nt], ah, bl2);
                mma_tf32(sacc[nt], ah, bh2);
            }
        }

        // ---- epilogue: acosh score + online softmax (fast math) ----
        float mx0 = -INFINITY, mx1 = -INFINITY;
        #pragma unroll
        for (int nt = 0; nt < 8; nt++) {
            #pragma unroll
            for (int e = 0; e < 4; e++) {
                int j  = j0 + nt * 8 + 2 * tig + (e & 1);
                int tr = (e < 2) ? t0 : t1;
                float s;
                if (j > tr) s = -INFINITY;
                else {
                    float v = fmaxf(sacc[nt][e], 1.0f + 1e-7f);
                    float dd = __logf(v + sqrtf(v * v - 1.f));
                    s = -dd * dd * 0.125f;
                }
                sacc[nt][e] = s;
                if (e < 2) mx0 = fmaxf(mx0, s); else mx1 = fmaxf(mx1, s);
            }
        }
        mx0 = fmaxf(mx0, __shfl_xor_sync(0xffffffffu, mx0, 1));
        mx0 = fmaxf(mx0, __shfl_xor_sync(0xffffffffu, mx0, 2));
        mx1 = fmaxf(mx1, __shfl_xor_sync(0xffffffffu, mx1, 1));
        mx1 = fmaxf(mx1, __shfl_xor_sync(0xffffffffu, mx1, 2));
        float mn0 = fmaxf(m0, mx0), mn1 = fmaxf(m1, mx1);
        float al0 = (mn0 == -INFINITY) ? 0.f : __expf(m0 - mn0);
        float al1 = (mn1 == -INFINITY) ? 0.f : __expf(m1 - mn1);
        m0 = mn0; m1 = mn1;

        float ps0 = 0.f, ps1 = 0.f;
        #pragma unroll
        for (int nt = 0; nt < 8; nt++) {
            float p0 = (mn0 == -INFINITY) ? 0.f : __expf(sacc[nt][0] - mn0);
            float p1 = (mn0 == -INFINITY) ? 0.f : __expf(sacc[nt][1] - mn0);
            float p2 = (mn1 == -INFINITY) ? 0.f : __expf(sacc[nt][2] - mn1);
            float p3 = (mn1 == -INFINITY) ? 0.f : __expf(sacc[nt][3] - mn1);
            sacc[nt][0] = p0; sacc[nt][1] = p1; sacc[nt][2] = p2; sacc[nt][3] = p3;
            ps0 += p0 + p1; ps1 += p2 + p3;
        }
        l0 = l0 * al0 + ps0;
        l1 = l1 * al1 + ps1;
        #pragma unroll
        for (int nt = 0; nt < 8; nt++) {
            yacc[nt][0] *= al0; yacc[nt][1] *= al0;
            yacc[nt][2] *= al1; yacc[nt][3] *= al1;
        }

        // ---- P fragments in registers (bf16 2-plane) ----
        uint32_t ph[4][4], pl[4][4];
        #pragma unroll
        for (int kc = 0; kc < 4; kc++) {
            split2(sacc[2 * kc][0],     sacc[2 * kc][1],     ph[kc][0], pl[kc][0]);
            split2(sacc[2 * kc][2],     sacc[2 * kc][3],     ph[kc][1], pl[kc][1]);
            split2(sacc[2 * kc + 1][0], sacc[2 * kc + 1][1], ph[kc][2], pl[kc][2]);
            split2(sacc[2 * kc + 1][2], sacc[2 * kc + 1][3], ph[kc][3], pl[kc][3]);
        }

        // ---- y += P . V  (bf16 m16n8k16, V pre-split) ----
        #pragma unroll
        for (int kc = 0; kc < 4; kc++) {
            #pragma unroll
            for (int nt = 0; nt < 8; nt++) {
                const uint32_t* pvh = cVh + (kc * 8 + tig) * 72 + nt * 8 + gid;
                const uint32_t* pvl = cVl + (kc * 8 + tig) * 72 + nt * 8 + gid;
                uint32_t vh[2], vl[2];
                vh[0] = pvh[0]; vh[1] = pvh[4 * 72];
                vl[0] = pvl[0]; vl[1] = pvl[4 * 72];
                mma_bf16(yacc[nt], ph[kc], vl);
                mma_bf16(yacc[nt], pl[kc], vh);
                mma_bf16(yacc[nt], ph[kc], vh);
            }
        }
    }

    // ---- finalize ----
    l0 += __shfl_xor_sync(0xffffffffu, l0, 1);
    l0 += __shfl_xor_sync(0xffffffffu, l0, 2);
    l1 += __shfl_xor_sync(0xffffffffu, l1, 1);
    l1 += __shfl_xor_sync(0xffffffffu, l1, 2);
    float inv0 = 1.f / l0, inv1 = 1.f / l1;
    #pragma unroll
    for (int nt = 0; nt < 8; nt++) {
        int col = h * 64 + nt * 8 + 2 * tig;
        if (t0 >= 0)
            *reinterpret_cast<float2*>(g_y + (long long)(b * Tn + t0) * Cn + col)
                = make_float2(yacc[nt][0] * inv0, yacc[nt][1] * inv0);
        if (t1 >= 0)
            *reinterpret_cast<float2*>(g_y + (long long)(b * Tn + t1) * Cn + col)
                = make_float2(yacc[nt][2] * inv1, yacc[nt][3] * inv1);
    }
}

// ---------------- fill non-spiking out rows with bias ---------------------
__global__ void fill_out(const float* __restrict__ bias, float* __restrict__ out) {
    int row = blockIdx.x;
    if (g_spike[row] > 0.f) return;
    float4* o = reinterpret_cast<float4*>(out + (long long)row * Cn);
    const float4* bv = reinterpret_cast<const float4*>(bias);
    for (int i = threadIdx.x; i < Cn / 4; i += blockDim.x) o[i] = bv[i];
}

// ---------------- launch ---------------------------------------------------
extern "C" void kernel_launch(void* const* d_in, const int* in_sizes, int n_in,
                              void* d_out, int out_size) {
    const float* x     = (const float*)d_in[0];
    const float* W_qkv = (const float*)d_in[1];
    const float* b_qkv = (const float*)d_in[2];
    const float* W_out = (const float*)d_in[3];
    const float* b_out = (const float*)d_in[4];
    const float* w_sur = (const float*)d_in[5];
    const float* b_sur = (const float*)d_in[6];
    const float* thr   = (const float*)d_in[7];
    float* out = (float*)d_out;

    float* p_qkv;
    cudaGetSymbolAddress((void**)&p_qkv, g_qkv);

    const int smem128 = (2 * 128 * 36 + 2 * 32 * 132) * 4;          // 70656
    const int smemFl  = 34816 + 69632 + 36864 + 512;                 // 141824
    cudaFuncSetAttribute(mma_gemm,   cudaFuncAttributeMaxDynamicSharedMemorySize, smem128);
    cudaFuncSetAttribute(mma_gemm_q, cudaFuncAttributeMaxDynamicSharedMemorySize, smem128);
    cudaFuncSetAttribute(mma_gemm_o, cudaFuncAttributeMaxDynamicSharedMemorySize, smem128);
    cudaFuncSetAttribute(flash_kernel, cudaFuncAttributeMaxDynamicSharedMemorySize, smemFl);

    // 1) spike gate + compaction
    spike_kernel<<<BT, 128>>>(x, w_sur, b_sur, thr);
    compact_kernel<<<Bn, Tn>>>();

    // 2) KV GEMM (dense, all rows, cols 1024..3071)
    mma_gemm<<<dim3(16, BT / 128, 1), 256, smem128>>>(
        x, Cn, W_qkv + Cn, NQKV, p_qkv + Cn, NQKV, Cn, b_qkv + Cn);

    // 3) Q GEMM (gathered spiking rows, cols 0..1023)
    mma_gemm_q<<<dim3(8, 32, 1), 256, smem128>>>(x, W_qkv, p_qkv, b_qkv);

    // 4) expmap + operand pre-split
    expmap_kernel<<<(BH * Tn / 2) / 8, 256>>>();

    // 5) fused attention over compacted spiking queries
    flash_kernel<<<dim3(Tn / 128, BH), 256, smemFl>>>();

    // 6) non-spiking out rows = bias
    fill_out<<<BT, 256>>>(b_out, out);

    // 7) output GEMM (gathered spiking rows, bf16 2-plane)
    mma_gemm_o<<<dim3(8, 32, 1), 256, smem128>>>(W_out, out, b_out);
}